// round 6
// baseline (speedup 1.0000x reference)
#include <cuda_runtime.h>

#define NN 100000
#define EE 1600000
#define FF 128
#define DD 64
#define GG 512
#define TM 96   // rows per CTA tile

// ---------------- device scratch ----------------
__device__ __align__(16) float g_y[NN * DD];     // projected features
__device__ __align__(16) float g_z[NN * DD];     // relu(y_self + agg + b1)
__device__ __align__(16) float g_h[NN * DD];     // layer-0 pre-BN relu output
__device__ int g_deg[NN];
__device__ int g_cur[NN];
__device__ int g_rowptr[NN + 1];
__device__ int g_cnt[GG];
__device__ __align__(8) int2 g_epack[EE];        // (src, weight bits) CSR-ordered
__device__ double g_sum[DD];
__device__ double g_sq[DD];
__device__ __align__(16) float g_bnp0[2 * DD];   // [scale, shift]
__device__ __align__(16) float g_bnp1[2 * DD];
__device__ __align__(16) float g_pool[2 * GG * DD];  // RAW h pooled sums

__device__ __forceinline__ void red4(float4* p, float x, float y, float z, float w) {
    asm volatile("red.global.add.v4.f32 [%0], {%1,%2,%3,%4};"
                 :: "l"(p), "f"(x), "f"(y), "f"(z), "f"(w) : "memory");
}

// ---------------- zero scratch (once per launch) ----------------
__global__ void zero_kernel() {
    int t = blockIdx.x * blockDim.x + threadIdx.x;
    if (t < NN) g_deg[t] = 0;
    if (t < GG) g_cnt[t] = 0;
    if (t < DD) { g_sum[t] = 0.0; g_sq[t] = 0.0; }
    if (t < 2 * GG * 16)
        reinterpret_cast<float4*>(g_pool)[t] = make_float4(0.f, 0.f, 0.f, 0.f);
}

// ---------------- degree histogram + per-graph node counts ----------------
__global__ void hist_kernel(const int* __restrict__ ei, const int* __restrict__ batch) {
    int t = blockIdx.x * blockDim.x + threadIdx.x;
    if (t < EE) atomicAdd(&g_deg[ei[EE + t]], 1);
    if (t < NN) atomicAdd(&g_cnt[batch[t]], 1);
}

// ---------------- single-block exclusive scan -> rowptr, cursor ----------------
__global__ void scan_kernel() {
    __shared__ int part[512];
    const int CH = (NN + 511) / 512;  // 196
    int tid = threadIdx.x;
    int base = tid * CH;
    int s = 0;
    for (int i = 0; i < CH; i++) {
        int n = base + i;
        if (n < NN) s += g_deg[n];
    }
    part[tid] = s;
    __syncthreads();
    for (int off = 1; off < 512; off <<= 1) {
        int v = (tid >= off) ? part[tid - off] : 0;
        __syncthreads();
        part[tid] += v;
        __syncthreads();
    }
    int run = (tid == 0) ? 0 : part[tid - 1];
    for (int i = 0; i < CH; i++) {
        int n = base + i;
        if (n < NN) {
            g_rowptr[n] = run;
            g_cur[n] = run;
            run += g_deg[n];
        }
    }
    if (tid == 511) g_rowptr[NN] = run;
}

// ---------------- CSR fill: epack[pos] = (src, w) ----------------
__global__ void fill_kernel(const int* __restrict__ ei, const float* __restrict__ ew) {
    int t = blockIdx.x * blockDim.x + threadIdx.x;
    if (t >= EE) return;
    int src = ei[t];
    int dst = ei[EE + t];
    float w = ew[t];
    int pos = atomicAdd(&g_cur[dst], 1);
    g_epack[pos] = make_int2(src, __float_as_int(w));
}

// ============ unified GEMM: C[TM x 64] tile of A[N x K] @ W[K x 64] ============
// MODE 0: A = A_in (K=128 or 64), write g_y
// MODE 1: A = g_h with BN0 scale/shift on load (K=64), write g_y
// MODE 2: A = g_z (K=64), epilogue relu+bias, store g_h, BN stats, pooling
// MODE 3: same as 2 but no g_h store
template <int K, int MODE>
__global__ __launch_bounds__(256) void gemm_kernel(
    const float* __restrict__ A_in, const float* __restrict__ W,
    const float* __restrict__ bias, const int* __restrict__ batch, int layer) {
    __shared__ float As[TM * 68];    // 26112 B
    __shared__ float Ws[64 * 64];    // 16384 B
    __shared__ float s_stat[128];
    const float* A = (MODE == 1) ? g_h : (MODE >= 2 ? g_z : A_in);
    const int KF4 = K / 4;
    int base = blockIdx.x * TM;
    int tid = threadIdx.x;
    int ty = tid >> 4, tx = tid & 15;   // ty: 16 groups of 6 rows; tx: 16 groups of 4 cols
    if (MODE >= 2 && tid < 128) s_stat[tid] = 0.f;
    float acc[6][4] = {};
    for (int kc = 0; kc < K; kc += 64) {
        // stage A chunk [TM x 64]
        for (int i = tid; i < TM * 16; i += 256) {
            int n = i >> 4, k4 = i & 15;
            int gn = base + n;
            float4 v = make_float4(0.f, 0.f, 0.f, 0.f);
            if (gn < NN) v = reinterpret_cast<const float4*>(A)[(size_t)gn * KF4 + (kc >> 2) + k4];
            if (MODE == 1) {
                float4 sc = reinterpret_cast<const float4*>(g_bnp0)[k4];
                float4 sh = reinterpret_cast<const float4*>(g_bnp0)[16 + k4];
                v.x = v.x * sc.x + sh.x; v.y = v.y * sc.y + sh.y;
                v.z = v.z * sc.z + sh.z; v.w = v.w * sc.w + sh.w;
            }
            *reinterpret_cast<float4*>(&As[n * 68 + k4 * 4]) = v;
        }
        // stage W chunk [64 x 64]
        for (int i = tid; i < 1024; i += 256)
            reinterpret_cast<float4*>(Ws)[i] =
                reinterpret_cast<const float4*>(W)[(size_t)(kc >> 2) * 16 * 4 + i];
        __syncthreads();
#pragma unroll 4
        for (int k = 0; k < 64; k++) {
            float a[6];
#pragma unroll
            for (int r = 0; r < 6; r++) a[r] = As[(ty * 6 + r) * 68 + k];
            float4 b = *reinterpret_cast<const float4*>(&Ws[k * 64 + tx * 4]);
            float bv[4] = {b.x, b.y, b.z, b.w};
#pragma unroll
            for (int r = 0; r < 6; r++)
#pragma unroll
                for (int c = 0; c < 4; c++) acc[r][c] += a[r] * bv[c];
        }
        __syncthreads();
    }
    if (MODE <= 1) {
#pragma unroll
        for (int r = 0; r < 6; r++) {
            int gn = base + ty * 6 + r;
            if (gn < NN)
                reinterpret_cast<float4*>(g_y)[gn * 16 + tx] =
                    make_float4(acc[r][0], acc[r][1], acc[r][2], acc[r][3]);
        }
    } else {
        float4 bb = *reinterpret_cast<const float4*>(&bias[tx * 4]);
        float bbv[4] = {bb.x, bb.y, bb.z, bb.w};
        float cs[4] = {0.f, 0.f, 0.f, 0.f};
        float cq[4] = {0.f, 0.f, 0.f, 0.f};
#pragma unroll
        for (int r = 0; r < 6; r++) {
            int gn = base + ty * 6 + r;
            if (gn < NN) {
                float v[4];
#pragma unroll
                for (int c = 0; c < 4; c++) {
                    v[c] = fmaxf(acc[r][c] + bbv[c], 0.f);
                    cs[c] += v[c];
                    cq[c] += v[c] * v[c];
                }
                if (MODE == 2)
                    reinterpret_cast<float4*>(g_h)[gn * 16 + tx] =
                        make_float4(v[0], v[1], v[2], v[3]);
                int g = batch[gn];
                red4(&reinterpret_cast<float4*>(g_pool)[(layer * GG + g) * 16 + tx],
                     v[0], v[1], v[2], v[3]);
            }
        }
        // lane l and l^16 share tx -> pre-reduce before smem atomics
#pragma unroll
        for (int c = 0; c < 4; c++) {
            cs[c] += __shfl_xor_sync(0xFFFFFFFFu, cs[c], 16);
            cq[c] += __shfl_xor_sync(0xFFFFFFFFu, cq[c], 16);
        }
        if ((tid & 31) < 16) {
#pragma unroll
            for (int c = 0; c < 4; c++) {
                atomicAdd(&s_stat[tx * 4 + c], cs[c]);
                atomicAdd(&s_stat[64 + tx * 4 + c], cq[c]);
            }
        }
        __syncthreads();
        if (tid < 64) {
            atomicAdd(&g_sum[tid], (double)s_stat[tid]);
            atomicAdd(&g_sq[tid], (double)s_stat[64 + tid]);
        }
    }
}

// ---------------- CSR aggregation: g_z = relu(y_self + sum w*y[src] + b1) ----------------
__global__ void agg_kernel(const float* __restrict__ b1) {
    int t = blockIdx.x * blockDim.x + threadIdx.x;
    int node = t >> 4, c = t & 15;
    if (node >= NN) return;
    int start = g_rowptr[node];
    int end = g_rowptr[node + 1];
    const float4* Y4 = reinterpret_cast<const float4*>(g_y);
    float4 acc = Y4[node * 16 + c];
    int i = start;
    for (; i + 2 <= end; i += 2) {
        int2 e0 = g_epack[i];
        int2 e1 = g_epack[i + 1];
        float4 v0 = Y4[e0.x * 16 + c];
        float4 v1 = Y4[e1.x * 16 + c];
        float w0 = __int_as_float(e0.y);
        float w1 = __int_as_float(e1.y);
        acc.x += w0 * v0.x + w1 * v1.x;
        acc.y += w0 * v0.y + w1 * v1.y;
        acc.z += w0 * v0.z + w1 * v1.z;
        acc.w += w0 * v0.w + w1 * v1.w;
    }
    if (i < end) {
        int2 e0 = g_epack[i];
        float4 v0 = Y4[e0.x * 16 + c];
        float w0 = __int_as_float(e0.y);
        acc.x += w0 * v0.x; acc.y += w0 * v0.y;
        acc.z += w0 * v0.z; acc.w += w0 * v0.w;
    }
    float4 bb = reinterpret_cast<const float4*>(b1)[c];
    reinterpret_cast<float4*>(g_z)[node * 16 + c] =
        make_float4(fmaxf(acc.x + bb.x, 0.f), fmaxf(acc.y + bb.y, 0.f),
                    fmaxf(acc.z + bb.z, 0.f), fmaxf(acc.w + bb.w, 0.f));
}

// ---------------- BN finalize -> scale/shift; reset stats ----------------
__global__ void bn_fin_kernel(const float* __restrict__ gamma, const float* __restrict__ beta,
                              int layer) {
    int f = threadIdx.x;
    if (f >= DD) return;
    double s = g_sum[f], q = g_sq[f];
    g_sum[f] = 0.0; g_sq[f] = 0.0;
    float mu = (float)(s / (double)NN);
    float var = (float)(q / (double)NN) - mu * mu;
    float rstd = rsqrtf(var + 1e-5f);
    float sc = gamma[f] * rstd;
    float* bp = layer ? g_bnp1 : g_bnp0;
    bp[f] = sc;
    bp[DD + f] = beta[f] - mu * sc;
}

// ---------------- classifier head: BN-corrected pooling + MLP + log_softmax ----------------
__global__ void head_kernel(const float* __restrict__ wf, const float* __restrict__ bf,
                            const float* __restrict__ wf1, const float* __restrict__ bf1,
                            const float* __restrict__ wf2, const float* __restrict__ bf2,
                            float* __restrict__ out) {
    __shared__ float gs[128];
    __shared__ float as_[64];
    __shared__ float bs[64];
    int g = blockIdx.x;
    int j = threadIdx.x;
    float cnt = (float)g_cnt[g];
    gs[j]      = g_pool[g * 64 + j] * g_bnp0[j] + cnt * g_bnp0[64 + j];
    gs[64 + j] = g_pool[(GG + g) * 64 + j] * g_bnp1[j] + cnt * g_bnp1[64 + j];
    __syncthreads();
    float acc = bf[j];
#pragma unroll 8
    for (int k = 0; k < 128; k++) acc += gs[k] * wf[k * 64 + j];
    as_[j] = fmaxf(acc, 0.f);
    __syncthreads();
    acc = bf1[j];
#pragma unroll 8
    for (int k = 0; k < 64; k++) acc += as_[k] * wf1[k * 64 + j];
    bs[j] = fmaxf(acc, 0.f);
    __syncthreads();
    if (j == 0) {
        float l0 = bf2[0], l1 = bf2[1];
        for (int k = 0; k < 64; k++) {
            l0 += bs[k] * wf2[k * 2 + 0];
            l1 += bs[k] * wf2[k * 2 + 1];
        }
        float m = fmaxf(l0, l1);
        float lse = m + logf(expf(l0 - m) + expf(l1 - m));
        out[g * 2 + 0] = l0 - lse;
        out[g * 2 + 1] = l1 - lse;
    }
}

extern "C" void kernel_launch(void* const* d_in, const int* in_sizes, int n_in,
                              void* d_out, int out_size) {
    (void)in_sizes; (void)n_in; (void)out_size;
    const float* x     = (const float*)d_in[0];
    const int*   ei    = (const int*)d_in[1];
    const float* ew    = (const float*)d_in[2];
    const int*   batch = (const int*)d_in[3];
    const float* w1a = (const float*)d_in[4],  *b1a = (const float*)d_in[5];
    const float* w2a = (const float*)d_in[6],  *b2a = (const float*)d_in[7];
    const float* gamma0 = (const float*)d_in[8],  *beta0 = (const float*)d_in[9];
    const float* w1b = (const float*)d_in[10], *b1b = (const float*)d_in[11];
    const float* w2b = (const float*)d_in[12], *b2b = (const float*)d_in[13];
    const float* gamma1 = (const float*)d_in[14], *beta1 = (const float*)d_in[15];
    const float* wf  = (const float*)d_in[16], *bf  = (const float*)d_in[17];
    const float* wf1 = (const float*)d_in[18], *bf1 = (const float*)d_in[19];
    const float* wf2 = (const float*)d_in[20], *bf2 = (const float*)d_in[21];
    float* out = (float*)d_out;

    int nb = (NN + TM - 1) / TM;           // 1042
    int eb = (EE + 255) / 256;             // 6250
    int ab = (NN * 16 + 255) / 256;        // 6250
    int zb = (NN + 255) / 256;

    // ---- CSR build (reused by both layers) ----
    zero_kernel<<<zb, 256>>>();
    hist_kernel<<<eb, 256>>>(ei, batch);
    scan_kernel<<<1, 512>>>();
    fill_kernel<<<eb, 256>>>(ei, ew);

    // ---- layer 0 ----
    gemm_kernel<128, 0><<<nb, 256>>>(x, w1a, nullptr, nullptr, 0);   // y = x @ W1a
    agg_kernel<<<ab, 256>>>(b1a);                                    // z = relu(y + gather + b1a)
    gemm_kernel<64, 2><<<nb, 256>>>(nullptr, w2a, b2a, batch, 0);    // h, stats, pool
    bn_fin_kernel<<<1, 64>>>(gamma0, beta0, 0);

    // ---- layer 1 ----
    gemm_kernel<64, 1><<<nb, 256>>>(nullptr, w1b, nullptr, nullptr, 0);  // y = BN0(h) @ W1b
    agg_kernel<<<ab, 256>>>(b1b);
    gemm_kernel<64, 3><<<nb, 256>>>(nullptr, w2b, b2b, batch, 1);
    bn_fin_kernel<<<1, 64>>>(gamma1, beta1, 1);

    // ---- head ----
    head_kernel<<<GG, 64>>>(wf, bf, wf1, bf1, wf2, bf2, out);
}

// round 8
// speedup vs baseline: 1.0580x; 1.0580x over previous
#include <cuda_runtime.h>
#include <stdint.h>

#define NN 100000
#define EE 1600000
#define FF 128
#define DD 64
#define GG 512
#define TMM 128   // rows per CTA tile

// ---------------- device scratch ----------------
__device__ __align__(16) float g_y[NN * DD];
__device__ __align__(16) float g_z[NN * DD];
__device__ __align__(16) float g_h[NN * DD];
__device__ int g_deg[NN];
__device__ int g_cur[NN];
__device__ int g_rowptr[NN + 1];
__device__ int g_cnt[GG];
__device__ __align__(8) int2 g_epack[EE];
__device__ double g_sq[DD];
__device__ __align__(16) float g_bnp0[2 * DD];
__device__ __align__(16) float g_bnp1[2 * DD];
__device__ __align__(16) float g_pool[2 * GG * DD];

__device__ __forceinline__ void red2(float* p, float x, float y) {
    asm volatile("red.global.add.v2.f32 [%0], {%1,%2};" :: "l"(p), "f"(x), "f"(y) : "memory");
}
__device__ __forceinline__ uint32_t smem_u32(const void* p) {
    return (uint32_t)__cvta_generic_to_shared(p);
}
__device__ __forceinline__ void ldm_x4(uint32_t* a, uint32_t addr) {
    asm volatile("ldmatrix.sync.aligned.m8n8.x4.shared.b16 {%0,%1,%2,%3}, [%4];"
                 : "=r"(a[0]), "=r"(a[1]), "=r"(a[2]), "=r"(a[3]) : "r"(addr));
}
__device__ __forceinline__ void ldm_x2t(uint32_t* b, uint32_t addr) {
    asm volatile("ldmatrix.sync.aligned.m8n8.x2.trans.shared.b16 {%0,%1}, [%2];"
                 : "=r"(b[0]), "=r"(b[1]) : "r"(addr));
}
__device__ __forceinline__ void mma16816(float* c, const uint32_t* a, const uint32_t* b) {
    asm volatile("mma.sync.aligned.m16n8k16.row.col.f32.bf16.bf16.f32 "
                 "{%0,%1,%2,%3}, {%4,%5,%6,%7}, {%8,%9}, {%0,%1,%2,%3};"
                 : "+f"(c[0]), "+f"(c[1]), "+f"(c[2]), "+f"(c[3])
                 : "r"(a[0]), "r"(a[1]), "r"(a[2]), "r"(a[3]), "r"(b[0]), "r"(b[1]));
}
// pack two truncated-bf16 values into one u32 (lane a = low half, b = high half)
__device__ __forceinline__ uint32_t bfpack(float a, float b) {
    return (__float_as_uint(a) >> 16) | (__float_as_uint(b) & 0xFFFF0000u);
}
// truncated-bf16 high part of a float, as float (exact subtraction partner)
__device__ __forceinline__ float bfhi(float a) {
    return __uint_as_float(__float_as_uint(a) & 0xFFFF0000u);
}

// ---------------- zero scratch ----------------
__global__ void zero_kernel() {
    int t = blockIdx.x * blockDim.x + threadIdx.x;
    if (t < NN) g_deg[t] = 0;
    if (t < GG) g_cnt[t] = 0;
    if (t < DD) g_sq[t] = 0.0;
    if (t < 2 * GG * 16)
        reinterpret_cast<float4*>(g_pool)[t] = make_float4(0.f, 0.f, 0.f, 0.f);
}

// ---------------- degree histogram + per-graph node counts ----------------
__global__ void hist_kernel(const int* __restrict__ ei, const int* __restrict__ batch) {
    int t = blockIdx.x * blockDim.x + threadIdx.x;
    if (t < EE) atomicAdd(&g_deg[ei[EE + t]], 1);
    if (t < NN) atomicAdd(&g_cnt[batch[t]], 1);
}

// ---------------- single-block exclusive scan ----------------
__global__ void scan_kernel() {
    __shared__ int part[512];
    const int CH = (NN + 511) / 512;
    int tid = threadIdx.x;
    int base = tid * CH;
    int s = 0;
    for (int i = 0; i < CH; i++) {
        int n = base + i;
        if (n < NN) s += g_deg[n];
    }
    part[tid] = s;
    __syncthreads();
    for (int off = 1; off < 512; off <<= 1) {
        int v = (tid >= off) ? part[tid - off] : 0;
        __syncthreads();
        part[tid] += v;
        __syncthreads();
    }
    int run = (tid == 0) ? 0 : part[tid - 1];
    for (int i = 0; i < CH; i++) {
        int n = base + i;
        if (n < NN) {
            g_rowptr[n] = run;
            g_cur[n] = run;
            run += g_deg[n];
        }
    }
    if (tid == 511) g_rowptr[NN] = run;
}

// ---------------- CSR fill ----------------
__global__ void fill_kernel(const int* __restrict__ ei, const float* __restrict__ ew) {
    int t = blockIdx.x * blockDim.x + threadIdx.x;
    if (t >= EE) return;
    int src = ei[t];
    int dst = ei[EE + t];
    float w = ew[t];
    int pos = atomicAdd(&g_cur[dst], 1);
    g_epack[pos] = make_int2(src, __float_as_int(w));
}

// ============ tensor-core GEMM: C[128 x 64] tile of A[N x K] @ W[K x 64] ============
// split-bf16 3-pass: v = hi + lo exactly; compute Ah*Bh + Ah*Bl + Al*Bh.
// MODE 0: A = A_in, write g_y
// MODE 1: A = g_h with BN0 scale/shift on load, write g_y
// MODE 2: A = g_z, epilogue relu+bias, store g_h, Sum(h^2) stats, pooling
// MODE 3: like 2, no g_h store
template <int K, int MODE>
__global__ __launch_bounds__(256) void gemm_kernel(
    const float* __restrict__ A_in, const float* __restrict__ W,
    const float* __restrict__ bias, const int* __restrict__ batch, int layer) {
    // units: uint32 = 2 bf16. A row stride 20 u32 (= 40 bf16, 80B: conflict-free).
    const int LDA = 20, APL = TMM * LDA;
    const int LDW = 36, WPL = 32 * LDW;
    __shared__ uint32_t As[2 * TMM * LDA];   // hi plane then lo plane
    __shared__ uint32_t Ws[2 * 32 * LDW];
    __shared__ float s_sq[64];
    const float* A = (MODE == 1) ? g_h : ((MODE >= 2) ? g_z : A_in);
    const int KF4 = K / 4;
    int base = blockIdx.x * TMM;
    int tid = threadIdx.x;
    int wid = tid >> 5;
    int lane = tid & 31;
    if (MODE >= 2 && tid < 64) s_sq[tid] = 0.f;
    float acc[8][4];
#pragma unroll
    for (int nt = 0; nt < 8; nt++) {
        acc[nt][0] = 0.f; acc[nt][1] = 0.f; acc[nt][2] = 0.f; acc[nt][3] = 0.f;
    }
    for (int kc = 0; kc < K; kc += 32) {
        // stage A chunk [128 rows x 32 cols] as hi/lo bf16 planes
        for (int i = tid; i < TMM * 8; i += 256) {
            int n = i >> 3;
            int k4 = i & 7;
            int gn = base + n;
            float4 v = make_float4(0.f, 0.f, 0.f, 0.f);
            if (gn < NN) v = reinterpret_cast<const float4*>(A)[(size_t)gn * KF4 + (kc >> 2) + k4];
            if (MODE == 1) {
                int ci = (kc >> 2) + k4;
                float4 sc = reinterpret_cast<const float4*>(g_bnp0)[ci];
                float4 sh = reinterpret_cast<const float4*>(g_bnp0)[16 + ci];
                v.x = v.x * sc.x + sh.x;
                v.y = v.y * sc.y + sh.y;
                v.z = v.z * sc.z + sh.z;
                v.w = v.w * sc.w + sh.w;
            }
            int off = n * LDA + k4 * 2;
            As[off] = bfpack(v.x, v.y);
            As[off + 1] = bfpack(v.z, v.w);
            As[APL + off] = bfpack(v.x - bfhi(v.x), v.y - bfhi(v.y));
            As[APL + off + 1] = bfpack(v.z - bfhi(v.z), v.w - bfhi(v.w));
        }
        // stage W chunk [32 k-rows x 64 cols]
        for (int i = tid; i < 32 * 16; i += 256) {
            int k = i >> 4;
            int j4 = i & 15;
            float4 v = reinterpret_cast<const float4*>(W)[(size_t)(kc + k) * 16 + j4];
            int off = k * LDW + j4 * 2;
            Ws[off] = bfpack(v.x, v.y);
            Ws[off + 1] = bfpack(v.z, v.w);
            Ws[WPL + off] = bfpack(v.x - bfhi(v.x), v.y - bfhi(v.y));
            Ws[WPL + off + 1] = bfpack(v.z - bfhi(v.z), v.w - bfhi(v.w));
        }
        __syncthreads();
#pragma unroll
        for (int s = 0; s < 2; s++) {
            // A fragment: rows wid*16..+15, k = s*16..+15
            uint32_t ah[4], al[4];
            uint32_t aaddr = smem_u32(&As[(wid * 16 + (lane & 15)) * LDA + s * 8 + ((lane >> 4) << 2)]);
            ldm_x4(ah, aaddr);
            ldm_x4(al, aaddr + APL * 4);
#pragma unroll
            for (int nt = 0; nt < 8; nt++) {
                uint32_t bh[2], bl[2];
                uint32_t baddr = smem_u32(&Ws[(s * 16 + (lane & 15)) * LDW + nt * 4]);
                ldm_x2t(bh, baddr);
                ldm_x2t(bl, baddr + WPL * 4);
                mma16816(acc[nt], ah, bh);
                mma16816(acc[nt], ah, bl);
                mma16816(acc[nt], al, bh);
            }
        }
        __syncthreads();
    }
    // C fragment: row r0 = wid*16 + lane/4 (and +8), cols nt*8 + (lane%4)*2 + {0,1}
    int r0 = base + wid * 16 + (lane >> 2);
    int cb = (lane & 3) * 2;
    if (MODE <= 1) {
#pragma unroll
        for (int nt = 0; nt < 8; nt++) {
            int col = nt * 8 + cb;
            if (r0 < NN)
                *reinterpret_cast<float2*>(&g_y[r0 * 64 + col]) = make_float2(acc[nt][0], acc[nt][1]);
            if (r0 + 8 < NN)
                *reinterpret_cast<float2*>(&g_y[(r0 + 8) * 64 + col]) = make_float2(acc[nt][2], acc[nt][3]);
        }
    } else {
        float cq[8][2];
#pragma unroll
        for (int nt = 0; nt < 8; nt++) {
            cq[nt][0] = 0.f;
            cq[nt][1] = 0.f;
        }
#pragma unroll
        for (int nt = 0; nt < 8; nt++) {
            int col = nt * 8 + cb;
            float2 bb = *reinterpret_cast<const float2*>(&bias[col]);
#pragma unroll
            for (int h2 = 0; h2 < 2; h2++) {
                int r = r0 + h2 * 8;
                if (r < NN) {
                    float v0 = fmaxf(acc[nt][h2 * 2 + 0] + bb.x, 0.f);
                    float v1 = fmaxf(acc[nt][h2 * 2 + 1] + bb.y, 0.f);
                    if (MODE == 2)
                        *reinterpret_cast<float2*>(&g_h[r * 64 + col]) = make_float2(v0, v1);
                    int g = batch[r];
                    red2(&g_pool[(layer * GG + g) * 64 + col], v0, v1);
                    cq[nt][0] += v0 * v0;
                    cq[nt][1] += v1 * v1;
                }
            }
        }
#pragma unroll
        for (int nt = 0; nt < 8; nt++) {
#pragma unroll
            for (int q = 0; q < 2; q++) {
                cq[nt][q] += __shfl_xor_sync(0xFFFFFFFFu, cq[nt][q], 4);
                cq[nt][q] += __shfl_xor_sync(0xFFFFFFFFu, cq[nt][q], 8);
                cq[nt][q] += __shfl_xor_sync(0xFFFFFFFFu, cq[nt][q], 16);
            }
        }
        if (lane < 4) {
#pragma unroll
            for (int nt = 0; nt < 8; nt++) {
                atomicAdd(&s_sq[nt * 8 + cb], cq[nt][0]);
                atomicAdd(&s_sq[nt * 8 + cb + 1], cq[nt][1]);
            }
        }
        __syncthreads();
        if (tid < 64) atomicAdd(&g_sq[tid], (double)s_sq[tid]);
    }
}

// ---------------- CSR aggregation: g_z = relu(y_self + sum w*y[src] + b1) ----------------
__global__ void agg_kernel(const float* __restrict__ b1) {
    int t = blockIdx.x * blockDim.x + threadIdx.x;
    int node = t >> 4;
    int c = t & 15;
    if (node >= NN) return;
    int start = g_rowptr[node];
    int end = g_rowptr[node + 1];
    const float4* Y4 = reinterpret_cast<const float4*>(g_y);
    float4 acc = Y4[node * 16 + c];
    int i = start;
    for (; i + 2 <= end; i += 2) {
        int2 e0 = g_epack[i];
        int2 e1 = g_epack[i + 1];
        float4 v0 = Y4[e0.x * 16 + c];
        float4 v1 = Y4[e1.x * 16 + c];
        float w0 = __int_as_float(e0.y);
        float w1 = __int_as_float(e1.y);
        acc.x += w0 * v0.x + w1 * v1.x;
        acc.y += w0 * v0.y + w1 * v1.y;
        acc.z += w0 * v0.z + w1 * v1.z;
        acc.w += w0 * v0.w + w1 * v1.w;
    }
    if (i < end) {
        int2 e0 = g_epack[i];
        float4 v0 = Y4[e0.x * 16 + c];
        float w0 = __int_as_float(e0.y);
        acc.x += w0 * v0.x;
        acc.y += w0 * v0.y;
        acc.z += w0 * v0.z;
        acc.w += w0 * v0.w;
    }
    float4 bb = reinterpret_cast<const float4*>(b1)[c];
    reinterpret_cast<float4*>(g_z)[node * 16 + c] =
        make_float4(fmaxf(acc.x + bb.x, 0.f), fmaxf(acc.y + bb.y, 0.f),
                    fmaxf(acc.z + bb.z, 0.f), fmaxf(acc.w + bb.w, 0.f));
}

// ---------------- BN finalize: mean from pool, var from g_sq ----------------
__global__ void bn_fin_kernel(const float* __restrict__ gamma, const float* __restrict__ beta,
                              int layer) {
    int f = threadIdx.x;
    if (f >= DD) return;
    const float* pp = &g_pool[layer * GG * DD];
    float s = 0.f;
    for (int g = 0; g < GG; g++) s += pp[g * DD + f];
    double q = g_sq[f];
    g_sq[f] = 0.0;
    float mu = s / (float)NN;
    float var = (float)(q / (double)NN) - mu * mu;
    float rstd = rsqrtf(var + 1e-5f);
    float sc = gamma[f] * rstd;
    float* bp = layer ? g_bnp1 : g_bnp0;
    bp[f] = sc;
    bp[DD + f] = beta[f] - mu * sc;
}

// ---------------- classifier head ----------------
__global__ void head_kernel(const float* __restrict__ wf, const float* __restrict__ bf,
                            const float* __restrict__ wf1, const float* __restrict__ bf1,
                            const float* __restrict__ wf2, const float* __restrict__ bf2,
                            float* __restrict__ out) {
    __shared__ float gs[128];
    __shared__ float as_[64];
    __shared__ float bs[64];
    int g = blockIdx.x;
    int j = threadIdx.x;
    float cnt = (float)g_cnt[g];
    gs[j]      = g_pool[g * 64 + j] * g_bnp0[j] + cnt * g_bnp0[64 + j];
    gs[64 + j] = g_pool[(GG + g) * 64 + j] * g_bnp1[j] + cnt * g_bnp1[64 + j];
    __syncthreads();
    float acc = bf[j];
#pragma unroll 8
    for (int k = 0; k < 128; k++) acc += gs[k] * wf[k * 64 + j];
    as_[j] = fmaxf(acc, 0.f);
    __syncthreads();
    acc = bf1[j];
#pragma unroll 8
    for (int k = 0; k < 64; k++) acc += as_[k] * wf1[k * 64 + j];
    bs[j] = fmaxf(acc, 0.f);
    __syncthreads();
    if (j == 0) {
        float l0 = bf2[0], l1 = bf2[1];
        for (int k = 0; k < 64; k++) {
            l0 += bs[k] * wf2[k * 2 + 0];
            l1 += bs[k] * wf2[k * 2 + 1];
        }
        float m = fmaxf(l0, l1);
        float lse = m + logf(expf(l0 - m) + expf(l1 - m));
        out[g * 2 + 0] = l0 - lse;
        out[g * 2 + 1] = l1 - lse;
    }
}

extern "C" void kernel_launch(void* const* d_in, const int* in_sizes, int n_in,
                              void* d_out, int out_size) {
    (void)in_sizes; (void)n_in; (void)out_size;
    const float* x     = (const float*)d_in[0];
    const int*   ei    = (const int*)d_in[1];
    const float* ew    = (const float*)d_in[2];
    const int*   batch = (const int*)d_in[3];
    const float* w1a = (const float*)d_in[4];
    const float* b1a = (const float*)d_in[5];
    const float* w2a = (const float*)d_in[6];
    const float* b2a = (const float*)d_in[7];
    const float* gamma0 = (const float*)d_in[8];
    const float* beta0  = (const float*)d_in[9];
    const float* w1b = (const float*)d_in[10];
    const float* b1b = (const float*)d_in[11];
    const float* w2b = (const float*)d_in[12];
    const float* b2b = (const float*)d_in[13];
    const float* gamma1 = (const float*)d_in[14];
    const float* beta1  = (const float*)d_in[15];
    const float* wf  = (const float*)d_in[16];
    const float* bf  = (const float*)d_in[17];
    const float* wf1 = (const float*)d_in[18];
    const float* bf1 = (const float*)d_in[19];
    const float* wf2 = (const float*)d_in[20];
    const float* bf2 = (const float*)d_in[21];
    float* out = (float*)d_out;

    int nb = (NN + TMM - 1) / TMM;         // 782
    int eb = (EE + 255) / 256;             // 6250
    int ab = (NN * 16 + 255) / 256;        // 6250
    int zb = (NN + 255) / 256;

    // ---- CSR build ----
    zero_kernel<<<zb, 256>>>();
    hist_kernel<<<eb, 256>>>(ei, batch);
    scan_kernel<<<1, 512>>>();
    fill_kernel<<<eb, 256>>>(ei, ew);

    // ---- layer 0 ----
    gemm_kernel<128, 0><<<nb, 256>>>(x, w1a, (const float*)0, (const int*)0, 0);
    agg_kernel<<<ab, 256>>>(b1a);
    gemm_kernel<64, 2><<<nb, 256>>>((const float*)0, w2a, b2a, batch, 0);
    bn_fin_kernel<<<1, 64>>>(gamma0, beta0, 0);

    // ---- layer 1 ----
    gemm_kernel<64, 1><<<nb, 256>>>((const float*)0, w1b, (const float*)0, (const int*)0, 0);
    agg_kernel<<<ab, 256>>>(b1b);
    gemm_kernel<64, 3><<<nb, 256>>>((const float*)0, w2b, b2b, batch, 1);
    bn_fin_kernel<<<1, 64>>>(gamma1, beta1, 1);

    // ---- head ----
    head_kernel<<<GG, 64>>>(wf, bf, wf1, bf1, wf2, bf2, out);
}

// round 10
// speedup vs baseline: 1.3533x; 1.2791x over previous
#include <cuda_runtime.h>
#include <stdint.h>

#define NN 100000
#define EE 1600000
#define FF 128
#define DD 64
#define GG 512
#define TMM 128   // rows per CTA tile
#define AGG_CH 2048

// ---------------- device scratch ----------------
__device__ __align__(16) float g_y[NN * DD];
__device__ __align__(16) float g_z[NN * DD];
__device__ __align__(16) float g_h[NN * DD];
__device__ __align__(16) int g_deg[NN];
__device__ __align__(16) int g_cur[NN + 4];
__device__ __align__(16) int g_rowptr[NN + 4];
__device__ int g_cnt[GG];
__device__ __align__(8) int2 g_epack[EE];
__device__ double g_sq[DD];
__device__ __align__(16) float g_bnp0[2 * DD];
__device__ __align__(16) float g_bnp1[2 * DD];
__device__ __align__(16) float g_pool[2 * GG * DD];

__device__ __forceinline__ void red2(float* p, float x, float y) {
    asm volatile("red.global.add.v2.f32 [%0], {%1,%2};" :: "l"(p), "f"(x), "f"(y) : "memory");
}
__device__ __forceinline__ uint32_t smem_u32(const void* p) {
    return (uint32_t)__cvta_generic_to_shared(p);
}
__device__ __forceinline__ void ldm_x4(uint32_t* a, uint32_t addr) {
    asm volatile("ldmatrix.sync.aligned.m8n8.x4.shared.b16 {%0,%1,%2,%3}, [%4];"
                 : "=r"(a[0]), "=r"(a[1]), "=r"(a[2]), "=r"(a[3]) : "r"(addr));
}
__device__ __forceinline__ void ldm_x2t(uint32_t* b, uint32_t addr) {
    asm volatile("ldmatrix.sync.aligned.m8n8.x2.trans.shared.b16 {%0,%1}, [%2];"
                 : "=r"(b[0]), "=r"(b[1]) : "r"(addr));
}
__device__ __forceinline__ void mma16816(float* c, const uint32_t* a, const uint32_t* b) {
    asm volatile("mma.sync.aligned.m16n8k16.row.col.f32.bf16.bf16.f32 "
                 "{%0,%1,%2,%3}, {%4,%5,%6,%7}, {%8,%9}, {%0,%1,%2,%3};"
                 : "+f"(c[0]), "+f"(c[1]), "+f"(c[2]), "+f"(c[3])
                 : "r"(a[0]), "r"(a[1]), "r"(a[2]), "r"(a[3]), "r"(b[0]), "r"(b[1]));
}
__device__ __forceinline__ uint32_t bfpack(float a, float b) {
    return (__float_as_uint(a) >> 16) | (__float_as_uint(b) & 0xFFFF0000u);
}
__device__ __forceinline__ float bfhi(float a) {
    return __uint_as_float(__float_as_uint(a) & 0xFFFF0000u);
}

// ---------------- degree histogram + per-graph node counts ----------------
__global__ void hist_kernel(const int* __restrict__ ei, const int* __restrict__ batch) {
    int t = blockIdx.x * blockDim.x + threadIdx.x;
    if (t < EE) atomicAdd(&g_deg[ei[EE + t]], 1);
    if (t < NN) atomicAdd(&g_cnt[batch[t]], 1);
}

// ---------------- single-block exclusive scan (int4-vectorized) ----------------
__global__ void scan_kernel() {
    __shared__ int part[512];
    const int CH4 = 49;               // 512 * 49 int4 = 100352 elems >= NN
    int tid = threadIdx.x;
    int b4 = tid * CH4;
    const int4* D4 = reinterpret_cast<const int4*>(g_deg);
    const int NV4 = NN / 4;           // 25000
    int s = 0;
    for (int i = 0; i < CH4; i++) {
        int idx = b4 + i;
        if (idx < NV4) {
            int4 d = D4[idx];
            s += d.x + d.y + d.z + d.w;
        }
    }
    part[tid] = s;
    __syncthreads();
    for (int off = 1; off < 512; off <<= 1) {
        int v = (tid >= off) ? part[tid - off] : 0;
        __syncthreads();
        part[tid] += v;
        __syncthreads();
    }
    int run = (tid == 0) ? 0 : part[tid - 1];
    int4* R4 = reinterpret_cast<int4*>(g_rowptr);
    int4* C4 = reinterpret_cast<int4*>(g_cur);
    for (int i = 0; i < CH4; i++) {
        int idx = b4 + i;
        if (idx < NV4) {
            int4 d = D4[idx];
            int4 r;
            r.x = run;
            r.y = r.x + d.x;
            r.z = r.y + d.y;
            r.w = r.z + d.z;
            run = r.w + d.w;
            R4[idx] = r;
            C4[idx] = r;
        }
    }
    if (tid == 511) g_rowptr[NN] = run;
}

// ---------------- CSR fill ----------------
__global__ void fill_kernel(const int* __restrict__ ei, const float* __restrict__ ew) {
    int t = blockIdx.x * blockDim.x + threadIdx.x;
    if (t >= EE) return;
    int src = ei[t];
    int dst = ei[EE + t];
    float w = ew[t];
    int pos = atomicAdd(&g_cur[dst], 1);
    g_epack[pos] = make_int2(src, __float_as_int(w));
}

// ============ tensor-core GEMM: C[128 x 64] tile of A[N x K] @ W[K x 64] ============
// split-bf16 3-pass: Ah*Bh + Ah*Bl + Al*Bh.
// MODE 0: A = A_in, write g_y
// MODE 1: A = g_h with BN0 scale/shift on load, write g_y
// MODE 2: A = g_z, epilogue relu+bias, store g_h, Sum(h^2) stats, pooling
// MODE 3: like 2, no g_h store
template <int K, int MODE>
__global__ __launch_bounds__(256) void gemm_kernel(
    const float* __restrict__ A_in, const float* __restrict__ W,
    const float* __restrict__ bias, const int* __restrict__ batch, int layer) {
    const int LDA = 20, APL = TMM * LDA;
    const int LDW = 36, WPL = 32 * LDW;
    __shared__ uint32_t As[2 * TMM * LDA];
    __shared__ uint32_t Ws[2 * 32 * LDW];
    __shared__ float s_sq[64];
    const float* A = (MODE == 1) ? g_h : ((MODE >= 2) ? g_z : A_in);
    const int KF4 = K / 4;
    int base = blockIdx.x * TMM;
    int tid = threadIdx.x;
    int wid = tid >> 5;
    int lane = tid & 31;
    if (MODE >= 2 && tid < 64) s_sq[tid] = 0.f;
    float acc[8][4];
#pragma unroll
    for (int nt = 0; nt < 8; nt++) {
        acc[nt][0] = 0.f; acc[nt][1] = 0.f; acc[nt][2] = 0.f; acc[nt][3] = 0.f;
    }
    for (int kc = 0; kc < K; kc += 32) {
        for (int i = tid; i < TMM * 8; i += 256) {
            int n = i >> 3;
            int k4 = i & 7;
            int gn = base + n;
            float4 v = make_float4(0.f, 0.f, 0.f, 0.f);
            if (gn < NN) v = reinterpret_cast<const float4*>(A)[(size_t)gn * KF4 + (kc >> 2) + k4];
            if (MODE == 1) {
                int ci = (kc >> 2) + k4;
                float4 sc = reinterpret_cast<const float4*>(g_bnp0)[ci];
                float4 sh = reinterpret_cast<const float4*>(g_bnp0)[16 + ci];
                v.x = v.x * sc.x + sh.x;
                v.y = v.y * sc.y + sh.y;
                v.z = v.z * sc.z + sh.z;
                v.w = v.w * sc.w + sh.w;
            }
            int off = n * LDA + k4 * 2;
            As[off] = bfpack(v.x, v.y);
            As[off + 1] = bfpack(v.z, v.w);
            As[APL + off] = bfpack(v.x - bfhi(v.x), v.y - bfhi(v.y));
            As[APL + off + 1] = bfpack(v.z - bfhi(v.z), v.w - bfhi(v.w));
        }
        for (int i = tid; i < 32 * 16; i += 256) {
            int k = i >> 4;
            int j4 = i & 15;
            float4 v = reinterpret_cast<const float4*>(W)[(size_t)(kc + k) * 16 + j4];
            int off = k * LDW + j4 * 2;
            Ws[off] = bfpack(v.x, v.y);
            Ws[off + 1] = bfpack(v.z, v.w);
            Ws[WPL + off] = bfpack(v.x - bfhi(v.x), v.y - bfhi(v.y));
            Ws[WPL + off + 1] = bfpack(v.z - bfhi(v.z), v.w - bfhi(v.w));
        }
        __syncthreads();
#pragma unroll
        for (int s = 0; s < 2; s++) {
            uint32_t ah[4], al[4];
            uint32_t aaddr = smem_u32(&As[(wid * 16 + (lane & 15)) * LDA + s * 8 + ((lane >> 4) << 2)]);
            ldm_x4(ah, aaddr);
            ldm_x4(al, aaddr + APL * 4);
#pragma unroll
            for (int nt = 0; nt < 8; nt++) {
                uint32_t bh[2], bl[2];
                uint32_t baddr = smem_u32(&Ws[(s * 16 + (lane & 15)) * LDW + nt * 4]);
                ldm_x2t(bh, baddr);
                ldm_x2t(bl, baddr + WPL * 4);
                mma16816(acc[nt], ah, bh);
                mma16816(acc[nt], ah, bl);
                mma16816(acc[nt], al, bh);
            }
        }
        __syncthreads();
    }
    int r0 = base + wid * 16 + (lane >> 2);
    int cb = (lane & 3) * 2;
    if (MODE <= 1) {
#pragma unroll
        for (int nt = 0; nt < 8; nt++) {
            int col = nt * 8 + cb;
            if (r0 < NN)
                *reinterpret_cast<float2*>(&g_y[r0 * 64 + col]) = make_float2(acc[nt][0], acc[nt][1]);
            if (r0 + 8 < NN)
                *reinterpret_cast<float2*>(&g_y[(r0 + 8) * 64 + col]) = make_float2(acc[nt][2], acc[nt][3]);
        }
    } else {
        float cq[8][2];
#pragma unroll
        for (int nt = 0; nt < 8; nt++) {
            cq[nt][0] = 0.f;
            cq[nt][1] = 0.f;
        }
#pragma unroll
        for (int nt = 0; nt < 8; nt++) {
            int col = nt * 8 + cb;
            float2 bb = *reinterpret_cast<const float2*>(&bias[col]);
#pragma unroll
            for (int h2 = 0; h2 < 2; h2++) {
                int r = r0 + h2 * 8;
                if (r < NN) {
                    float v0 = fmaxf(acc[nt][h2 * 2 + 0] + bb.x, 0.f);
                    float v1 = fmaxf(acc[nt][h2 * 2 + 1] + bb.y, 0.f);
                    if (MODE == 2)
                        *reinterpret_cast<float2*>(&g_h[r * 64 + col]) = make_float2(v0, v1);
                    int g = batch[r];
                    red2(&g_pool[(layer * GG + g) * 64 + col], v0, v1);
                    cq[nt][0] += v0 * v0;
                    cq[nt][1] += v1 * v1;
                }
            }
        }
#pragma unroll
        for (int nt = 0; nt < 8; nt++) {
#pragma unroll
            for (int q = 0; q < 2; q++) {
                cq[nt][q] += __shfl_xor_sync(0xFFFFFFFFu, cq[nt][q], 4);
                cq[nt][q] += __shfl_xor_sync(0xFFFFFFFFu, cq[nt][q], 8);
                cq[nt][q] += __shfl_xor_sync(0xFFFFFFFFu, cq[nt][q], 16);
            }
        }
        if (lane < 4) {
#pragma unroll
            for (int nt = 0; nt < 8; nt++) {
                atomicAdd(&s_sq[nt * 8 + cb], cq[nt][0]);
                atomicAdd(&s_sq[nt * 8 + cb + 1], cq[nt][1]);
            }
        }
        __syncthreads();
        if (tid < 64) atomicAdd(&g_sq[tid], (double)s_sq[tid]);
    }
}

// ---------------- CSR aggregation, smem-staged edges ----------------
__global__ __launch_bounds__(256) void agg_kernel(const float* __restrict__ b1) {
    __shared__ int2 s_e[AGG_CH];
    __shared__ int s_ptr[17];
    int nb0 = blockIdx.x * 16;
    int tid = threadIdx.x;
    if (tid <= 16) {
        int n = nb0 + tid;
        s_ptr[tid] = g_rowptr[n > NN ? NN : n];
    }
    __syncthreads();
    int e0 = s_ptr[0];
    int e1 = s_ptr[16];
    int g16 = tid >> 4;
    int c = tid & 15;
    int node = nb0 + g16;
    bool valid = node < NN;
    int my_s = valid ? s_ptr[g16] : 0;
    int my_e = valid ? s_ptr[g16 + 1] : 0;
    const float4* Y4 = reinterpret_cast<const float4*>(g_y);
    float4 acc = valid ? Y4[node * 16 + c] : make_float4(0.f, 0.f, 0.f, 0.f);
    for (int cs = e0; cs < e1; cs += AGG_CH) {
        int ce = min(cs + AGG_CH, e1);
        __syncthreads();
        for (int i = tid; i < ce - cs; i += 256) s_e[i] = g_epack[cs + i];
        __syncthreads();
        int lo = max(my_s, cs);
        int hi = min(my_e, ce);
        int i = lo;
        for (; i + 2 <= hi; i += 2) {
            int2 ea = s_e[i - cs];
            int2 eb = s_e[i + 1 - cs];
            float4 va = Y4[ea.x * 16 + c];
            float4 vb = Y4[eb.x * 16 + c];
            float wa = __int_as_float(ea.y);
            float wb = __int_as_float(eb.y);
            acc.x += wa * va.x + wb * vb.x;
            acc.y += wa * va.y + wb * vb.y;
            acc.z += wa * va.z + wb * vb.z;
            acc.w += wa * va.w + wb * vb.w;
        }
        if (i < hi) {
            int2 ea = s_e[i - cs];
            float4 va = Y4[ea.x * 16 + c];
            float wa = __int_as_float(ea.y);
            acc.x += wa * va.x;
            acc.y += wa * va.y;
            acc.z += wa * va.z;
            acc.w += wa * va.w;
        }
    }
    if (valid) {
        float4 bb = reinterpret_cast<const float4*>(b1)[c];
        reinterpret_cast<float4*>(g_z)[node * 16 + c] =
            make_float4(fmaxf(acc.x + bb.x, 0.f), fmaxf(acc.y + bb.y, 0.f),
                        fmaxf(acc.z + bb.z, 0.f), fmaxf(acc.w + bb.w, 0.f));
    }
}

// ---------------- BN finalize: mean from pool, var from g_sq; RESET stats ----------------
__global__ void bn_fin_kernel(const float* __restrict__ gamma, const float* __restrict__ beta,
                              int layer) {
    int f = threadIdx.x;
    if (f >= DD) return;
    const float* pp = &g_pool[layer * GG * DD];
    float s0 = 0.f, s1 = 0.f, s2 = 0.f, s3 = 0.f;
    for (int g = 0; g < GG; g += 4) {
        s0 += pp[(g + 0) * DD + f];
        s1 += pp[(g + 1) * DD + f];
        s2 += pp[(g + 2) * DD + f];
        s3 += pp[(g + 3) * DD + f];
    }
    float s = (s0 + s1) + (s2 + s3);
    double q = g_sq[f];
    g_sq[f] = 0.0;                    // reset for next layer (and idempotent per launch)
    float mu = s / (float)NN;
    float var = (float)(q / (double)NN) - mu * mu;
    float rstd = rsqrtf(var + 1e-5f);
    float sc = gamma[f] * rstd;
    float* bp = layer ? g_bnp1 : g_bnp0;
    bp[f] = sc;
    bp[DD + f] = beta[f] - mu * sc;
}

// ---------------- classifier head ----------------
__global__ void head_kernel(const float* __restrict__ wf, const float* __restrict__ bf,
                            const float* __restrict__ wf1, const float* __restrict__ bf1,
                            const float* __restrict__ wf2, const float* __restrict__ bf2,
                            float* __restrict__ out) {
    __shared__ float gs[128];
    __shared__ float as_[64];
    __shared__ float bs[64];
    int g = blockIdx.x;
    int j = threadIdx.x;
    float cnt = (float)g_cnt[g];
    gs[j]      = g_pool[g * 64 + j] * g_bnp0[j] + cnt * g_bnp0[64 + j];
    gs[64 + j] = g_pool[(GG + g) * 64 + j] * g_bnp1[j] + cnt * g_bnp1[64 + j];
    __syncthreads();
    float acc = bf[j];
#pragma unroll 8
    for (int k = 0; k < 128; k++) acc += gs[k] * wf[k * 64 + j];
    as_[j] = fmaxf(acc, 0.f);
    __syncthreads();
    acc = bf1[j];
#pragma unroll 8
    for (int k = 0; k < 64; k++) acc += as_[k] * wf1[k * 64 + j];
    bs[j] = fmaxf(acc, 0.f);
    __syncthreads();
    if (j == 0) {
        float l0 = bf2[0], l1 = bf2[1];
        for (int k = 0; k < 64; k++) {
            l0 += bs[k] * wf2[k * 2 + 0];
            l1 += bs[k] * wf2[k * 2 + 1];
        }
        float m = fmaxf(l0, l1);
        float lse = m + logf(expf(l0 - m) + expf(l1 - m));
        out[g * 2 + 0] = l0 - lse;
        out[g * 2 + 1] = l1 - lse;
    }
}

extern "C" void kernel_launch(void* const* d_in, const int* in_sizes, int n_in,
                              void* d_out, int out_size) {
    (void)in_sizes; (void)n_in; (void)out_size;
    const float* x     = (const float*)d_in[0];
    const int*   ei    = (const int*)d_in[1];
    const float* ew    = (const float*)d_in[2];
    const int*   batch = (const int*)d_in[3];
    const float* w1a = (const float*)d_in[4];
    const float* b1a = (const float*)d_in[5];
    const float* w2a = (const float*)d_in[6];
    const float* b2a = (const float*)d_in[7];
    const float* gamma0 = (const float*)d_in[8];
    const float* beta0  = (const float*)d_in[9];
    const float* w1b = (const float*)d_in[10];
    const float* b1b = (const float*)d_in[11];
    const float* w2b = (const float*)d_in[12];
    const float* b2b = (const float*)d_in[13];
    const float* gamma1 = (const float*)d_in[14];
    const float* beta1  = (const float*)d_in[15];
    const float* wf  = (const float*)d_in[16];
    const float* bf  = (const float*)d_in[17];
    const float* wf1 = (const float*)d_in[18];
    const float* bf1 = (const float*)d_in[19];
    const float* wf2 = (const float*)d_in[20];
    const float* bf2 = (const float*)d_in[21];
    float* out = (float*)d_out;

    int nb = (NN + TMM - 1) / TMM;         // 782
    int eb = (EE + 255) / 256;             // 6250
    int ab = (NN + 15) / 16;               // 6250

    void *p_deg, *p_cnt, *p_sq, *p_pool;
    cudaGetSymbolAddress(&p_deg, g_deg);
    cudaGetSymbolAddress(&p_cnt, g_cnt);
    cudaGetSymbolAddress(&p_sq, g_sq);
    cudaGetSymbolAddress(&p_pool, g_pool);
    cudaMemsetAsync(p_deg, 0, NN * sizeof(int));
    cudaMemsetAsync(p_cnt, 0, GG * sizeof(int));
    cudaMemsetAsync(p_sq, 0, DD * sizeof(double));
    cudaMemsetAsync(p_pool, 0, 2 * GG * DD * sizeof(float));

    // ---- CSR build ----
    hist_kernel<<<eb, 256>>>(ei, batch);
    scan_kernel<<<1, 512>>>();
    fill_kernel<<<eb, 256>>>(ei, ew);

    // ---- layer 0 ----
    gemm_kernel<128, 0><<<nb, 256>>>(x, w1a, (const float*)0, (const int*)0, 0);
    agg_kernel<<<ab, 256>>>(b1a);
    gemm_kernel<64, 2><<<nb, 256>>>((const float*)0, w2a, b2a, batch, 0);
    bn_fin_kernel<<<1, 64>>>(gamma0, beta0, 0);

    // ---- layer 1 ----
    gemm_kernel<64, 1><<<nb, 256>>>((const float*)0, w1b, (const float*)0, (const int*)0, 0);
    agg_kernel<<<ab, 256>>>(b1b);
    gemm_kernel<64, 3><<<nb, 256>>>((const float*)0, w2b, b2b, batch, 1);
    bn_fin_kernel<<<1, 64>>>(gamma1, beta1, 1);

    // ---- head ----
    head_kernel<<<GG, 64>>>(wf, bf, wf1, bf1, wf2, bf2, out);
}

// round 11
// speedup vs baseline: 1.4722x; 1.0879x over previous
#include <cuda_runtime.h>
#include <stdint.h>

#define NN 100000
#define EE 1600000
#define FF 128
#define DD 64
#define GG 512
#define TMM 128   // rows per CTA tile
#define AGG_CH 2048

// ---------------- device scratch ----------------
__device__ __align__(16) float g_y[NN * DD];
__device__ __align__(16) float g_z[NN * DD];
__device__ __align__(16) float g_h[NN * DD];
__device__ __align__(16) int g_deg[NN];
__device__ __align__(16) int g_cur[NN + 4];
__device__ __align__(16) int g_rowptr[NN + 4];
__device__ int g_cnt[GG];
__device__ __align__(8) int2 g_epack[EE];
__device__ double g_sq[DD];
__device__ __align__(16) float g_bnp0[2 * DD];
__device__ __align__(16) float g_bnp1[2 * DD];
__device__ __align__(16) float g_pool[2 * GG * DD];

__device__ __forceinline__ void red1(float* p, float x) {
    asm volatile("red.global.add.f32 [%0], %1;" :: "l"(p), "f"(x) : "memory");
}
__device__ __forceinline__ uint32_t smem_u32(const void* p) {
    return (uint32_t)__cvta_generic_to_shared(p);
}
__device__ __forceinline__ void ldm_x4(uint32_t* a, uint32_t addr) {
    asm volatile("ldmatrix.sync.aligned.m8n8.x4.shared.b16 {%0,%1,%2,%3}, [%4];"
                 : "=r"(a[0]), "=r"(a[1]), "=r"(a[2]), "=r"(a[3]) : "r"(addr));
}
__device__ __forceinline__ void ldm_x2t(uint32_t* b, uint32_t addr) {
    asm volatile("ldmatrix.sync.aligned.m8n8.x2.trans.shared.b16 {%0,%1}, [%2];"
                 : "=r"(b[0]), "=r"(b[1]) : "r"(addr));
}
__device__ __forceinline__ void mma16816(float* c, const uint32_t* a, const uint32_t* b) {
    asm volatile("mma.sync.aligned.m16n8k16.row.col.f32.bf16.bf16.f32 "
                 "{%0,%1,%2,%3}, {%4,%5,%6,%7}, {%8,%9}, {%0,%1,%2,%3};"
                 : "+f"(c[0]), "+f"(c[1]), "+f"(c[2]), "+f"(c[3])
                 : "r"(a[0]), "r"(a[1]), "r"(a[2]), "r"(a[3]), "r"(b[0]), "r"(b[1]));
}
__device__ __forceinline__ uint32_t bfpack(float a, float b) {
    return (__float_as_uint(a) >> 16) | (__float_as_uint(b) & 0xFFFF0000u);
}
__device__ __forceinline__ float bfhi(float a) {
    return __uint_as_float(__float_as_uint(a) & 0xFFFF0000u);
}

// ---------------- single-block exclusive scan (int4), zeroes g_deg after use ----------------
__global__ void scan_kernel() {
    __shared__ int part[512];
    const int CH4 = 49;               // 512 * 49 int4 = 100352 elems >= NN
    int tid = threadIdx.x;
    int b4 = tid * CH4;
    int4* D4 = reinterpret_cast<int4*>(g_deg);
    const int NV4 = NN / 4;           // 25000
    int s = 0;
    for (int i = 0; i < CH4; i++) {
        int idx = b4 + i;
        if (idx < NV4) {
            int4 d = D4[idx];
            s += d.x + d.y + d.z + d.w;
        }
    }
    part[tid] = s;
    __syncthreads();
    for (int off = 1; off < 512; off <<= 1) {
        int v = (tid >= off) ? part[tid - off] : 0;
        __syncthreads();
        part[tid] += v;
        __syncthreads();
    }
    int run = (tid == 0) ? 0 : part[tid - 1];
    int4* R4 = reinterpret_cast<int4*>(g_rowptr);
    int4* C4 = reinterpret_cast<int4*>(g_cur);
    for (int i = 0; i < CH4; i++) {
        int idx = b4 + i;
        if (idx < NV4) {
            int4 d = D4[idx];
            int4 r;
            r.x = run;
            r.y = r.x + d.x;
            r.z = r.y + d.y;
            r.w = r.z + d.z;
            run = r.w + d.w;
            R4[idx] = r;
            C4[idx] = r;
            D4[idx] = make_int4(0, 0, 0, 0);   // self-clean for next launch
        }
    }
    if (tid == 511) g_rowptr[NN] = run;
}

// ---------------- CSR fill ----------------
__global__ void fill_kernel(const int* __restrict__ ei, const float* __restrict__ ew) {
    int t = blockIdx.x * blockDim.x + threadIdx.x;
    if (t >= EE) return;
    int src = ei[t];
    int dst = ei[EE + t];
    float w = ew[t];
    int pos = atomicAdd(&g_cur[dst], 1);
    g_epack[pos] = make_int2(src, __float_as_int(w));
}

// ============ tensor-core GEMM: C[128 x 64] tile of A[N x K] @ W[K x 64] ============
// split-bf16 3-pass: Ah*Bh + Ah*Bl + Al*Bh.
// MODE 0: A = A_in, write g_y. If hist_ei != null, blocks >= nb_gemm do the degree histogram.
// MODE 1: A = g_h with BN0 scale/shift on load, write g_y
// MODE 2: A = g_z, epilogue relu+bias, store g_h, stats + pooling via sorted-batch column pass
// MODE 3: like 2, no g_h store
template <int K, int MODE>
__global__ __launch_bounds__(256) void gemm_kernel(
    const float* __restrict__ A_in, const float* __restrict__ W,
    const float* __restrict__ bias, const int* __restrict__ batch, int layer,
    const int* __restrict__ hist_ei, int nb_gemm) {
    const int LDA = 20, APL = TMM * LDA;       // u32 units
    const int LDW = 36, WPL = 32 * LDW;
    __shared__ __align__(16) char s_buf[35840];  // As+Ws (29696B) mainloop / Ht (34816B) epilogue
    __shared__ float s_sq[64];
    __shared__ int s_g[TMM];
    uint32_t* As = reinterpret_cast<uint32_t*>(s_buf);
    uint32_t* Ws = reinterpret_cast<uint32_t*>(s_buf + 2 * TMM * LDA * 4);
    float* Ht = reinterpret_cast<float*>(s_buf);

    // fused degree histogram blocks (MODE 0 only)
    if (MODE == 0 && hist_ei != 0 && (int)blockIdx.x >= nb_gemm) {
        int t = (blockIdx.x - nb_gemm) * 256 + threadIdx.x;
        if (t < EE) atomicAdd(&g_deg[hist_ei[EE + t]], 1);
        if (t < NN) atomicAdd(&g_cnt[batch[t]], 1);
        return;
    }

    const float* A = (MODE == 1) ? g_h : ((MODE >= 2) ? g_z : A_in);
    const int KF4 = K / 4;
    int base = blockIdx.x * TMM;
    int tid = threadIdx.x;
    int wid = tid >> 5;
    int lane = tid & 31;
    if (MODE >= 2) {
        if (tid < 64) s_sq[tid] = 0.f;
        for (int i = tid; i < TMM; i += 256) {
            int gn = base + i;
            s_g[i] = batch[gn < NN ? gn : NN - 1];
        }
    }
    float acc[8][4];
#pragma unroll
    for (int nt = 0; nt < 8; nt++) {
        acc[nt][0] = 0.f; acc[nt][1] = 0.f; acc[nt][2] = 0.f; acc[nt][3] = 0.f;
    }
    for (int kc = 0; kc < K; kc += 32) {
        for (int i = tid; i < TMM * 8; i += 256) {
            int n = i >> 3;
            int k4 = i & 7;
            int gn = base + n;
            float4 v = make_float4(0.f, 0.f, 0.f, 0.f);
            if (gn < NN) v = reinterpret_cast<const float4*>(A)[(size_t)gn * KF4 + (kc >> 2) + k4];
            if (MODE == 1) {
                int ci = (kc >> 2) + k4;
                float4 sc = reinterpret_cast<const float4*>(g_bnp0)[ci];
                float4 sh = reinterpret_cast<const float4*>(g_bnp0)[16 + ci];
                v.x = v.x * sc.x + sh.x;
                v.y = v.y * sc.y + sh.y;
                v.z = v.z * sc.z + sh.z;
                v.w = v.w * sc.w + sh.w;
            }
            int off = n * LDA + k4 * 2;
            As[off] = bfpack(v.x, v.y);
            As[off + 1] = bfpack(v.z, v.w);
            As[APL + off] = bfpack(v.x - bfhi(v.x), v.y - bfhi(v.y));
            As[APL + off + 1] = bfpack(v.z - bfhi(v.z), v.w - bfhi(v.w));
        }
        for (int i = tid; i < 32 * 16; i += 256) {
            int k = i >> 4;
            int j4 = i & 15;
            float4 v = reinterpret_cast<const float4*>(W)[(size_t)(kc + k) * 16 + j4];
            int off = k * LDW + j4 * 2;
            Ws[off] = bfpack(v.x, v.y);
            Ws[off + 1] = bfpack(v.z, v.w);
            Ws[WPL + off] = bfpack(v.x - bfhi(v.x), v.y - bfhi(v.y));
            Ws[WPL + off + 1] = bfpack(v.z - bfhi(v.z), v.w - bfhi(v.w));
        }
        __syncthreads();
#pragma unroll
        for (int s = 0; s < 2; s++) {
            uint32_t ah[4], al[4];
            uint32_t aaddr = smem_u32(&As[(wid * 16 + (lane & 15)) * LDA + s * 8 + ((lane >> 4) << 2)]);
            ldm_x4(ah, aaddr);
            ldm_x4(al, aaddr + APL * 4);
#pragma unroll
            for (int nt = 0; nt < 8; nt++) {
                uint32_t bh[2], bl[2];
                uint32_t baddr = smem_u32(&Ws[(s * 16 + (lane & 15)) * LDW + nt * 4]);
                ldm_x2t(bh, baddr);
                ldm_x2t(bl, baddr + WPL * 4);
                mma16816(acc[nt], ah, bh);
                mma16816(acc[nt], ah, bl);
                mma16816(acc[nt], al, bh);
            }
        }
        __syncthreads();
    }
    int rl0 = wid * 16 + (lane >> 2);          // local row
    int r0 = base + rl0;
    int cb = (lane & 3) * 2;
    if (MODE <= 1) {
#pragma unroll
        for (int nt = 0; nt < 8; nt++) {
            int col = nt * 8 + cb;
            if (r0 < NN)
                *reinterpret_cast<float2*>(&g_y[r0 * 64 + col]) = make_float2(acc[nt][0], acc[nt][1]);
            if (r0 + 8 < NN)
                *reinterpret_cast<float2*>(&g_y[(r0 + 8) * 64 + col]) = make_float2(acc[nt][2], acc[nt][3]);
        }
    } else {
        // write relu(bias+acc) tile into smem (Ht), plus g_h store for MODE 2
#pragma unroll
        for (int nt = 0; nt < 8; nt++) {
            int col = nt * 8 + cb;
            float2 bb = *reinterpret_cast<const float2*>(&bias[col]);
#pragma unroll
            for (int h2 = 0; h2 < 2; h2++) {
                int rl = rl0 + h2 * 8;
                int r = base + rl;
                float v0 = 0.f, v1 = 0.f;
                if (r < NN) {
                    v0 = fmaxf(acc[nt][h2 * 2 + 0] + bb.x, 0.f);
                    v1 = fmaxf(acc[nt][h2 * 2 + 1] + bb.y, 0.f);
                    if (MODE == 2)
                        *reinterpret_cast<float2*>(&g_h[r * 64 + col]) = make_float2(v0, v1);
                }
                *reinterpret_cast<float2*>(&Ht[rl * 68 + col]) = make_float2(v0, v1);
            }
        }
        __syncthreads();
        // column pass: pooling via sorted-batch run flushes + sum of squares
        int col = tid & 63;
        int rs = (tid >> 6) * 32;
        float* poolL = &g_pool[layer * GG * DD];
        float ps = 0.f, pq = 0.f;
        int cg = s_g[rs];
#pragma unroll 4
        for (int r = rs; r < rs + 32; r++) {
            float v = Ht[r * 68 + col];
            int gr = s_g[r];
            if (gr != cg) {
                red1(&poolL[cg * 64 + col], ps);
                ps = 0.f;
                cg = gr;
            }
            ps += v;
            pq += v * v;
        }
        red1(&poolL[cg * 64 + col], ps);
        atomicAdd(&s_sq[col], pq);
        __syncthreads();
        if (tid < 64) atomicAdd(&g_sq[tid], (double)s_sq[tid]);
    }
}

// ---------------- CSR aggregation, smem-staged edges ----------------
__global__ __launch_bounds__(256) void agg_kernel(const float* __restrict__ b1) {
    __shared__ int2 s_e[AGG_CH];
    __shared__ int s_ptr[17];
    int nb0 = blockIdx.x * 16;
    int tid = threadIdx.x;
    if (tid <= 16) {
        int n = nb0 + tid;
        s_ptr[tid] = g_rowptr[n > NN ? NN : n];
    }
    __syncthreads();
    int e0 = s_ptr[0];
    int e1 = s_ptr[16];
    int g16 = tid >> 4;
    int c = tid & 15;
    int node = nb0 + g16;
    bool valid = node < NN;
    int my_s = valid ? s_ptr[g16] : 0;
    int my_e = valid ? s_ptr[g16 + 1] : 0;
    const float4* Y4 = reinterpret_cast<const float4*>(g_y);
    float4 acc = valid ? Y4[node * 16 + c] : make_float4(0.f, 0.f, 0.f, 0.f);
    for (int cs = e0; cs < e1; cs += AGG_CH) {
        int ce = min(cs + AGG_CH, e1);
        __syncthreads();
        for (int i = tid; i < ce - cs; i += 256) s_e[i] = g_epack[cs + i];
        __syncthreads();
        int lo = max(my_s, cs);
        int hi = min(my_e, ce);
        int i = lo;
        for (; i + 2 <= hi; i += 2) {
            int2 ea = s_e[i - cs];
            int2 eb = s_e[i + 1 - cs];
            float4 va = Y4[ea.x * 16 + c];
            float4 vb = Y4[eb.x * 16 + c];
            float wa = __int_as_float(ea.y);
            float wb = __int_as_float(eb.y);
            acc.x += wa * va.x + wb * vb.x;
            acc.y += wa * va.y + wb * vb.y;
            acc.z += wa * va.z + wb * vb.z;
            acc.w += wa * va.w + wb * vb.w;
        }
        if (i < hi) {
            int2 ea = s_e[i - cs];
            float4 va = Y4[ea.x * 16 + c];
            float wa = __int_as_float(ea.y);
            acc.x += wa * va.x;
            acc.y += wa * va.y;
            acc.z += wa * va.z;
            acc.w += wa * va.w;
        }
    }
    if (valid) {
        float4 bb = reinterpret_cast<const float4*>(b1)[c];
        reinterpret_cast<float4*>(g_z)[node * 16 + c] =
            make_float4(fmaxf(acc.x + bb.x, 0.f), fmaxf(acc.y + bb.y, 0.f),
                        fmaxf(acc.z + bb.z, 0.f), fmaxf(acc.w + bb.w, 0.f));
    }
}

// ---------------- BN finalize: mean from pool, var from g_sq; resets g_sq ----------------
__global__ void bn_fin_kernel(const float* __restrict__ gamma, const float* __restrict__ beta,
                              int layer) {
    int f = threadIdx.x;
    if (f >= DD) return;
    const float* pp = &g_pool[layer * GG * DD];
    float s0 = 0.f, s1 = 0.f, s2 = 0.f, s3 = 0.f;
    for (int g = 0; g < GG; g += 4) {
        s0 += pp[(g + 0) * DD + f];
        s1 += pp[(g + 1) * DD + f];
        s2 += pp[(g + 2) * DD + f];
        s3 += pp[(g + 3) * DD + f];
    }
    float s = (s0 + s1) + (s2 + s3);
    double q = g_sq[f];
    g_sq[f] = 0.0;
    float mu = s / (float)NN;
    float var = (float)(q / (double)NN) - mu * mu;
    float rstd = rsqrtf(var + 1e-5f);
    float sc = gamma[f] * rstd;
    float* bp = layer ? g_bnp1 : g_bnp0;
    bp[f] = sc;
    bp[DD + f] = beta[f] - mu * sc;
}

// ---------------- classifier head; self-cleans g_pool and g_cnt ----------------
__global__ void head_kernel(const float* __restrict__ wf, const float* __restrict__ bf,
                            const float* __restrict__ wf1, const float* __restrict__ bf1,
                            const float* __restrict__ wf2, const float* __restrict__ bf2,
                            float* __restrict__ out) {
    __shared__ float gs[128];
    __shared__ float as_[64];
    __shared__ float bs[64];
    int g = blockIdx.x;
    int j = threadIdx.x;
    float cnt = (float)g_cnt[g];
    gs[j]      = g_pool[g * 64 + j] * g_bnp0[j] + cnt * g_bnp0[64 + j];
    gs[64 + j] = g_pool[(GG + g) * 64 + j] * g_bnp1[j] + cnt * g_bnp1[64 + j];
    // self-clean for next launch
    g_pool[g * 64 + j] = 0.f;
    g_pool[(GG + g) * 64 + j] = 0.f;
    if (j == 0) g_cnt[g] = 0;
    __syncthreads();
    float acc = bf[j];
#pragma unroll 8
    for (int k = 0; k < 128; k++) acc += gs[k] * wf[k * 64 + j];
    as_[j] = fmaxf(acc, 0.f);
    __syncthreads();
    acc = bf1[j];
#pragma unroll 8
    for (int k = 0; k < 64; k++) acc += as_[k] * wf1[k * 64 + j];
    bs[j] = fmaxf(acc, 0.f);
    __syncthreads();
    if (j == 0) {
        float l0 = bf2[0], l1 = bf2[1];
        for (int k = 0; k < 64; k++) {
            l0 += bs[k] * wf2[k * 2 + 0];
            l1 += bs[k] * wf2[k * 2 + 1];
        }
        float m = fmaxf(l0, l1);
        float lse = m + logf(expf(l0 - m) + expf(l1 - m));
        out[g * 2 + 0] = l0 - lse;
        out[g * 2 + 1] = l1 - lse;
    }
}

extern "C" void kernel_launch(void* const* d_in, const int* in_sizes, int n_in,
                              void* d_out, int out_size) {
    (void)in_sizes; (void)n_in; (void)out_size;
    const float* x     = (const float*)d_in[0];
    const int*   ei    = (const int*)d_in[1];
    const float* ew    = (const float*)d_in[2];
    const int*   batch = (const int*)d_in[3];
    const float* w1a = (const float*)d_in[4];
    const float* b1a = (const float*)d_in[5];
    const float* w2a = (const float*)d_in[6];
    const float* b2a = (const float*)d_in[7];
    const float* gamma0 = (const float*)d_in[8];
    const float* beta0  = (const float*)d_in[9];
    const float* w1b = (const float*)d_in[10];
    const float* b1b = (const float*)d_in[11];
    const float* w2b = (const float*)d_in[12];
    const float* b2b = (const float*)d_in[13];
    const float* gamma1 = (const float*)d_in[14];
    const float* beta1  = (const float*)d_in[15];
    const float* wf  = (const float*)d_in[16];
    const float* bf  = (const float*)d_in[17];
    const float* wf1 = (const float*)d_in[18];
    const float* bf1 = (const float*)d_in[19];
    const float* wf2 = (const float*)d_in[20];
    const float* bf2 = (const float*)d_in[21];
    float* out = (float*)d_out;

    int nb = (NN + TMM - 1) / TMM;         // 782
    int eb = (EE + 255) / 256;             // 6250
    int ab = (NN + 15) / 16;               // 6250

    // ---- layer 0 projection + fused degree/count histogram ----
    gemm_kernel<128, 0><<<nb + eb, 256>>>(x, w1a, (const float*)0, batch, 0, ei, nb);
    scan_kernel<<<1, 512>>>();
    fill_kernel<<<eb, 256>>>(ei, ew);
    agg_kernel<<<ab, 256>>>(b1a);
    gemm_kernel<64, 2><<<nb, 256>>>((const float*)0, w2a, b2a, batch, 0, (const int*)0, nb);
    bn_fin_kernel<<<1, 64>>>(gamma0, beta0, 0);

    // ---- layer 1 ----
    gemm_kernel<64, 1><<<nb, 256>>>((const float*)0, w1b, (const float*)0, batch, 0, (const int*)0, nb);
    agg_kernel<<<ab, 256>>>(b1b);
    gemm_kernel<64, 3><<<nb, 256>>>((const float*)0, w2b, b2b, batch, 1, (const int*)0, nb);
    bn_fin_kernel<<<1, 64>>>(gamma1, beta1, 1);

    // ---- head ----
    head_kernel<<<GG, 64>>>(wf, bf, wf1, bf1, wf2, bf2, out);
}

// round 13
// speedup vs baseline: 1.5100x; 1.0257x over previous
#include <cuda_runtime.h>
#include <stdint.h>

#define NN 100000
#define EE 1600000
#define FF 128
#define DD 64
#define GG 512
#define TMM 128   // rows per CTA tile
#define AGG_CH 2048

// ---------------- device scratch ----------------
__device__ __align__(16) float g_y[NN * DD];
__device__ __align__(16) float g_z[NN * DD];
__device__ __align__(16) float g_h[NN * DD];
__device__ __align__(16) int g_deg[NN];
__device__ __align__(16) int g_cur[NN + 4];
__device__ __align__(16) int g_rowptr[NN + 4];
__device__ int g_cnt[GG];
__device__ __align__(8) int2 g_epack[EE];
__device__ double g_sq[DD];
__device__ __align__(16) float g_bnp0[2 * DD];
__device__ __align__(16) float g_bnp1[2 * DD];
__device__ __align__(16) float g_pool[2 * GG * DD];

__device__ __forceinline__ void red1(float* p, float x) {
    asm volatile("red.global.add.f32 [%0], %1;" :: "l"(p), "f"(x) : "memory");
}
__device__ __forceinline__ uint32_t smem_u32(const void* p) {
    return (uint32_t)__cvta_generic_to_shared(p);
}
__device__ __forceinline__ void ldm_x4(uint32_t* a, uint32_t addr) {
    asm volatile("ldmatrix.sync.aligned.m8n8.x4.shared.b16 {%0,%1,%2,%3}, [%4];"
                 : "=r"(a[0]), "=r"(a[1]), "=r"(a[2]), "=r"(a[3]) : "r"(addr));
}
__device__ __forceinline__ void ldm_x2t(uint32_t* b, uint32_t addr) {
    asm volatile("ldmatrix.sync.aligned.m8n8.x2.trans.shared.b16 {%0,%1}, [%2];"
                 : "=r"(b[0]), "=r"(b[1]) : "r"(addr));
}
__device__ __forceinline__ void mma16816(float* c, const uint32_t* a, const uint32_t* b) {
    asm volatile("mma.sync.aligned.m16n8k16.row.col.f32.bf16.bf16.f32 "
                 "{%0,%1,%2,%3}, {%4,%5,%6,%7}, {%8,%9}, {%0,%1,%2,%3};"
                 : "+f"(c[0]), "+f"(c[1]), "+f"(c[2]), "+f"(c[3])
                 : "r"(a[0]), "r"(a[1]), "r"(a[2]), "r"(a[3]), "r"(b[0]), "r"(b[1]));
}
__device__ __forceinline__ uint32_t bfpack(float a, float b) {
    return (__float_as_uint(a) >> 16) | (__float_as_uint(b) & 0xFFFF0000u);
}
__device__ __forceinline__ float bfhi(float a) {
    return __uint_as_float(__float_as_uint(a) & 0xFFFF0000u);
}

// ---------------- single-block exclusive scan (int4), zeroes g_deg after use ----------------
__global__ void scan_kernel() {
    __shared__ int part[512];
    const int CH4 = 49;
    int tid = threadIdx.x;
    int b4 = tid * CH4;
    int4* D4 = reinterpret_cast<int4*>(g_deg);
    const int NV4 = NN / 4;
    int s = 0;
    for (int i = 0; i < CH4; i++) {
        int idx = b4 + i;
        if (idx < NV4) {
            int4 d = D4[idx];
            s += d.x + d.y + d.z + d.w;
        }
    }
    part[tid] = s;
    __syncthreads();
    for (int off = 1; off < 512; off <<= 1) {
        int v = (tid >= off) ? part[tid - off] : 0;
        __syncthreads();
        part[tid] += v;
        __syncthreads();
    }
    int run = (tid == 0) ? 0 : part[tid - 1];
    int4* R4 = reinterpret_cast<int4*>(g_rowptr);
    int4* C4 = reinterpret_cast<int4*>(g_cur);
    for (int i = 0; i < CH4; i++) {
        int idx = b4 + i;
        if (idx < NV4) {
            int4 d = D4[idx];
            int4 r;
            r.x = run;
            r.y = r.x + d.x;
            r.z = r.y + d.y;
            r.w = r.z + d.z;
            run = r.w + d.w;
            R4[idx] = r;
            C4[idx] = r;
            D4[idx] = make_int4(0, 0, 0, 0);
        }
    }
    if (tid == 511) g_rowptr[NN] = run;
}

// ---------------- CSR fill: 4 edges/thread for atomic MLP ----------------
__global__ void fill_kernel(const int* __restrict__ ei, const float* __restrict__ ew) {
    int t0 = (blockIdx.x * 256 + threadIdx.x) * 4;
    int src[4], dst[4], pos[4];
    float w[4];
#pragma unroll
    for (int j = 0; j < 4; j++) {
        int e = t0 + j;
        if (e < EE) {
            src[j] = ei[e];
            dst[j] = ei[EE + e];
            w[j] = ew[e];
        }
    }
#pragma unroll
    for (int j = 0; j < 4; j++) {
        int e = t0 + j;
        if (e < EE) pos[j] = atomicAdd(&g_cur[dst[j]], 1);
    }
#pragma unroll
    for (int j = 0; j < 4; j++) {
        int e = t0 + j;
        if (e < EE) g_epack[pos[j]] = make_int2(src[j], __float_as_int(w[j]));
    }
}

// ============ tensor-core GEMM: C[128 x 64] tile of A[N x K] @ W[K x 64] ============
// split-bf16 3-pass: Ah*Bh + Ah*Bl + Al*Bh. Software-pipelined staging.
// MODE 0: A = A_in, write g_y. If hist_ei != null, blocks >= nb_gemm do the histogram.
// MODE 1: A = g_h with BN0 scale/shift on load, write g_y
// MODE 2: A = g_z, epilogue relu+bias, store g_h, stats + pooling via sorted-batch pass
// MODE 3: like 2, no g_h store
template <int K, int MODE>
__global__ __launch_bounds__(256) void gemm_kernel(
    const float* __restrict__ A_in, const float* __restrict__ W,
    const float* __restrict__ bias, const int* __restrict__ batch, int layer,
    const int* __restrict__ hist_ei, int nb_gemm) {
    const int LDA = 20, APL = TMM * LDA;
    const int LDW = 36, WPL = 32 * LDW;
    __shared__ __align__(16) char s_buf[35840];
    __shared__ float s_sq[64];
    __shared__ int s_g[TMM];
    uint32_t* As = reinterpret_cast<uint32_t*>(s_buf);
    uint32_t* Ws = reinterpret_cast<uint32_t*>(s_buf + 2 * TMM * LDA * 4);
    float* Ht = reinterpret_cast<float*>(s_buf);

    if (MODE == 0 && hist_ei != 0 && (int)blockIdx.x >= nb_gemm) {
        int t = (blockIdx.x - nb_gemm) * 256 + threadIdx.x;
        if (t < EE) atomicAdd(&g_deg[hist_ei[EE + t]], 1);
        if (t < NN) atomicAdd(&g_cnt[batch[t]], 1);
        return;
    }

    const float* A = (MODE == 1) ? g_h : ((MODE >= 2) ? g_z : A_in);
    const int KF4 = K / 4;
    int base = blockIdx.x * TMM;
    int tid = threadIdx.x;
    int wid = tid >> 5;
    int lane = tid & 31;
    if (MODE >= 2) {
        if (tid < 64) s_sq[tid] = 0.f;
        for (int i = tid; i < TMM; i += 256) {
            int gn = base + i;
            s_g[i] = batch[gn < NN ? gn : NN - 1];
        }
    }

    float4 ra[4];
    float4 rw[2];
    auto loadA = [&](int kc) {
#pragma unroll
        for (int it = 0; it < 4; it++) {
            int i = tid + it * 256;
            int n = i >> 3, k4 = i & 7;
            int gn = base + n;
            float4 v = make_float4(0.f, 0.f, 0.f, 0.f);
            if (gn < NN) v = reinterpret_cast<const float4*>(A)[(size_t)gn * KF4 + (kc >> 2) + k4];
            if (MODE == 1) {
                int ci = (kc >> 2) + k4;
                float4 sc = reinterpret_cast<const float4*>(g_bnp0)[ci];
                float4 sh = reinterpret_cast<const float4*>(g_bnp0)[16 + ci];
                v.x = v.x * sc.x + sh.x;
                v.y = v.y * sc.y + sh.y;
                v.z = v.z * sc.z + sh.z;
                v.w = v.w * sc.w + sh.w;
            }
            ra[it] = v;
        }
    };
    auto loadW = [&](int kc) {
#pragma unroll
        for (int it = 0; it < 2; it++) {
            int i = tid + it * 256;
            int k = i >> 4, j4 = i & 15;
            rw[it] = reinterpret_cast<const float4*>(W)[(size_t)(kc + k) * 16 + j4];
        }
    };
    auto storeAW = [&]() {
#pragma unroll
        for (int it = 0; it < 4; it++) {
            int i = tid + it * 256;
            int n = i >> 3, k4 = i & 7;
            float4 v = ra[it];
            int off = n * LDA + k4 * 2;
            As[off] = bfpack(v.x, v.y);
            As[off + 1] = bfpack(v.z, v.w);
            As[APL + off] = bfpack(v.x - bfhi(v.x), v.y - bfhi(v.y));
            As[APL + off + 1] = bfpack(v.z - bfhi(v.z), v.w - bfhi(v.w));
        }
#pragma unroll
        for (int it = 0; it < 2; it++) {
            int i = tid + it * 256;
            int k = i >> 4, j4 = i & 15;
            float4 v = rw[it];
            int off = k * LDW + j4 * 2;
            Ws[off] = bfpack(v.x, v.y);
            Ws[off + 1] = bfpack(v.z, v.w);
            Ws[WPL + off] = bfpack(v.x - bfhi(v.x), v.y - bfhi(v.y));
            Ws[WPL + off + 1] = bfpack(v.z - bfhi(v.z), v.w - bfhi(v.w));
        }
    };

    float acc[8][4];
#pragma unroll
    for (int nt = 0; nt < 8; nt++) {
        acc[nt][0] = 0.f; acc[nt][1] = 0.f; acc[nt][2] = 0.f; acc[nt][3] = 0.f;
    }

    loadA(0);
    loadW(0);
    for (int kc = 0; kc < K; kc += 32) {
        storeAW();
        __syncthreads();
        if (kc + 32 < K) {
            loadA(kc + 32);
            loadW(kc + 32);
        }
#pragma unroll
        for (int s = 0; s < 2; s++) {
            uint32_t ah[4], al[4];
            uint32_t aaddr = smem_u32(&As[(wid * 16 + (lane & 15)) * LDA + s * 8 + ((lane >> 4) << 2)]);
            ldm_x4(ah, aaddr);
            ldm_x4(al, aaddr + APL * 4);
#pragma unroll
            for (int nt = 0; nt < 8; nt++) {
                uint32_t bh[2], bl[2];
                uint32_t baddr = smem_u32(&Ws[(s * 16 + (lane & 15)) * LDW + nt * 4]);
                ldm_x2t(bh, baddr);
                ldm_x2t(bl, baddr + WPL * 4);
                mma16816(acc[nt], ah, bh);
                mma16816(acc[nt], ah, bl);
                mma16816(acc[nt], al, bh);
            }
        }
        __syncthreads();
    }

    int rl0 = wid * 16 + (lane >> 2);
    int r0 = base + rl0;
    int cb = (lane & 3) * 2;
    if (MODE <= 1) {
#pragma unroll
        for (int nt = 0; nt < 8; nt++) {
            int col = nt * 8 + cb;
            if (r0 < NN)
                *reinterpret_cast<float2*>(&g_y[r0 * 64 + col]) = make_float2(acc[nt][0], acc[nt][1]);
            if (r0 + 8 < NN)
                *reinterpret_cast<float2*>(&g_y[(r0 + 8) * 64 + col]) = make_float2(acc[nt][2], acc[nt][3]);
        }
    } else {
#pragma unroll
        for (int nt = 0; nt < 8; nt++) {
            int col = nt * 8 + cb;
            float2 bb = *reinterpret_cast<const float2*>(&bias[col]);
#pragma unroll
            for (int h2 = 0; h2 < 2; h2++) {
                int rl = rl0 + h2 * 8;
                int r = base + rl;
                float v0 = 0.f, v1 = 0.f;
                if (r < NN) {
                    v0 = fmaxf(acc[nt][h2 * 2 + 0] + bb.x, 0.f);
                    v1 = fmaxf(acc[nt][h2 * 2 + 1] + bb.y, 0.f);
                    if (MODE == 2)
                        *reinterpret_cast<float2*>(&g_h[r * 64 + col]) = make_float2(v0, v1);
                }
                *reinterpret_cast<float2*>(&Ht[rl * 68 + col]) = make_float2(v0, v1);
            }
        }
        __syncthreads();
        int col = tid & 63;
        int rs = (tid >> 6) * 32;
        float* poolL = &g_pool[layer * GG * DD];
        float ps = 0.f, pq = 0.f;
        int cg = s_g[rs];
#pragma unroll 4
        for (int r = rs; r < rs + 32; r++) {
            float v = Ht[r * 68 + col];
            int gr = s_g[r];
            if (gr != cg) {
                red1(&poolL[cg * 64 + col], ps);
                ps = 0.f;
                cg = gr;
            }
            ps += v;
            pq += v * v;
        }
        red1(&poolL[cg * 64 + col], ps);
        atomicAdd(&s_sq[col], pq);
        __syncthreads();
        if (tid < 64) atomicAdd(&g_sq[tid], (double)s_sq[tid]);
    }
}

// ---------------- CSR aggregation, smem-staged edges ----------------
__global__ __launch_bounds__(256) void agg_kernel(const float* __restrict__ b1) {
    __shared__ int2 s_e[AGG_CH];
    __shared__ int s_ptr[17];
    int nb0 = blockIdx.x * 16;
    int tid = threadIdx.x;
    if (tid <= 16) {
        int n = nb0 + tid;
        s_ptr[tid] = g_rowptr[n > NN ? NN : n];
    }
    __syncthreads();
    int e0 = s_ptr[0];
    int e1 = s_ptr[16];
    int g16 = tid >> 4;
    int c = tid & 15;
    int node = nb0 + g16;
    bool valid = node < NN;
    int my_s = valid ? s_ptr[g16] : 0;
    int my_e = valid ? s_ptr[g16 + 1] : 0;
    const float4* Y4 = reinterpret_cast<const float4*>(g_y);
    float4 acc = valid ? Y4[node * 16 + c] : make_float4(0.f, 0.f, 0.f, 0.f);
    for (int cs = e0; cs < e1; cs += AGG_CH) {
        int ce = min(cs + AGG_CH, e1);
        __syncthreads();
        for (int i = tid; i < ce - cs; i += 256) s_e[i] = g_epack[cs + i];
        __syncthreads();
        int lo = max(my_s, cs);
        int hi = min(my_e, ce);
        int i = lo;
        for (; i + 2 <= hi; i += 2) {
            int2 ea = s_e[i - cs];
            int2 eb = s_e[i + 1 - cs];
            float4 va = Y4[ea.x * 16 + c];
            float4 vb = Y4[eb.x * 16 + c];
            float wa = __int_as_float(ea.y);
            float wb = __int_as_float(eb.y);
            acc.x += wa * va.x + wb * vb.x;
            acc.y += wa * va.y + wb * vb.y;
            acc.z += wa * va.z + wb * vb.z;
            acc.w += wa * va.w + wb * vb.w;
        }
        if (i < hi) {
            int2 ea = s_e[i - cs];
            float4 va = Y4[ea.x * 16 + c];
            float wa = __int_as_float(ea.y);
            acc.x += wa * va.x;
            acc.y += wa * va.y;
            acc.z += wa * va.z;
            acc.w += wa * va.w;
        }
    }
    if (valid) {
        float4 bb = reinterpret_cast<const float4*>(b1)[c];
        reinterpret_cast<float4*>(g_z)[node * 16 + c] =
            make_float4(fmaxf(acc.x + bb.x, 0.f), fmaxf(acc.y + bb.y, 0.f),
                        fmaxf(acc.z + bb.z, 0.f), fmaxf(acc.w + bb.w, 0.f));
    }
}

// ---------------- BN finalize: mean from pool, var from g_sq; resets g_sq ----------------
__global__ void bn_fin_kernel(const float* __restrict__ gamma, const float* __restrict__ beta,
                              int layer) {
    int f = threadIdx.x;
    if (f >= DD) return;
    const float* pp = &g_pool[layer * GG * DD];
    float s0 = 0.f, s1 = 0.f, s2 = 0.f, s3 = 0.f;
    for (int g = 0; g < GG; g += 4) {
        s0 += pp[(g + 0) * DD + f];
        s1 += pp[(g + 1) * DD + f];
        s2 += pp[(g + 2) * DD + f];
        s3 += pp[(g + 3) * DD + f];
    }
    float s = (s0 + s1) + (s2 + s3);
    double q = g_sq[f];
    g_sq[f] = 0.0;
    float mu = s / (float)NN;
    float var = (float)(q / (double)NN) - mu * mu;
    float rstd = rsqrtf(var + 1e-5f);
    float sc = gamma[f] * rstd;
    float* bp = layer ? g_bnp1 : g_bnp0;
    bp[f] = sc;
    bp[DD + f] = beta[f] - mu * sc;
}

// ---------------- classifier head; self-cleans g_pool and g_cnt ----------------
__global__ void head_kernel(const float* __restrict__ wf, const float* __restrict__ bf,
                            const float* __restrict__ wf1, const float* __restrict__ bf1,
                            const float* __restrict__ wf2, const float* __restrict__ bf2,
                            float* __restrict__ out) {
    __shared__ float gs[128];
    __shared__ float as_[64];
    __shared__ float bs[64];
    int g = blockIdx.x;
    int j = threadIdx.x;
    float cnt = (float)g_cnt[g];
    gs[j]      = g_pool[g * 64 + j] * g_bnp0[j] + cnt * g_bnp0[64 + j];
    gs[64 + j] = g_pool[(GG + g) * 64 + j] * g_bnp1[j] + cnt * g_bnp1[64 + j];
    g_pool[g * 64 + j] = 0.f;
    g_pool[(GG + g) * 64 + j] = 0.f;
    if (j == 0) g_cnt[g] = 0;
    __syncthreads();
    float acc = bf[j];
#pragma unroll 8
    for (int k = 0; k < 128; k++) acc += gs[k] * wf[k * 64 + j];
    as_[j] = fmaxf(acc, 0.f);
    __syncthreads();
    acc = bf1[j];
#pragma unroll 8
    for (int k = 0; k < 64; k++) acc += as_[k] * wf1[k * 64 + j];
    bs[j] = fmaxf(acc, 0.f);
    __syncthreads();
    if (j == 0) {
        float l0 = bf2[0], l1 = bf2[1];
        for (int k = 0; k < 64; k++) {
            l0 += bs[k] * wf2[k * 2 + 0];
            l1 += bs[k] * wf2[k * 2 + 1];
        }
        float m = fmaxf(l0, l1);
        float lse = m + logf(expf(l0 - m) + expf(l1 - m));
        out[g * 2 + 0] = l0 - lse;
        out[g * 2 + 1] = l1 - lse;
    }
}

extern "C" void kernel_launch(void* const* d_in, const int* in_sizes, int n_in,
                              void* d_out, int out_size) {
    (void)in_sizes; (void)n_in; (void)out_size;
    const float* x     = (const float*)d_in[0];
    const int*   ei    = (const int*)d_in[1];
    const float* ew    = (const float*)d_in[2];
    const int*   batch = (const int*)d_in[3];
    const float* w1a = (const float*)d_in[4];
    const float* b1a = (const float*)d_in[5];
    const float* w2a = (const float*)d_in[6];
    const float* b2a = (const float*)d_in[7];
    const float* gamma0 = (const float*)d_in[8];
    const float* beta0  = (const float*)d_in[9];
    const float* w1b = (const float*)d_in[10];
    const float* b1b = (const float*)d_in[11];
    const float* w2b = (const float*)d_in[12];
    const float* b2b = (const float*)d_in[13];
    const float* gamma1 = (const float*)d_in[14];
    const float* beta1  = (const float*)d_in[15];
    const float* wf  = (const float*)d_in[16];
    const float* bf  = (const float*)d_in[17];
    const float* wf1 = (const float*)d_in[18];
    const float* bf1 = (const float*)d_in[19];
    const float* wf2 = (const float*)d_in[20];
    const float* bf2 = (const float*)d_in[21];
    float* out = (float*)d_out;

    int nb = (NN + TMM - 1) / TMM;         // 782
    int eb = (EE + 255) / 256;             // 6250
    int eb4 = (EE + 1023) / 1024;          // 1563
    int ab = (NN + 15) / 16;               // 6250

    // ---- layer 0 projection + fused degree/count histogram ----
    gemm_kernel<128, 0><<<nb + eb, 256>>>(x, w1a, (const float*)0, batch, 0, ei, nb);
    scan_kernel<<<1, 512>>>();
    fill_kernel<<<eb4, 256>>>(ei, ew);
    agg_kernel<<<ab, 256>>>(b1a);
    gemm_kernel<64, 2><<<nb, 256>>>((const float*)0, w2a, b2a, batch, 0, (const int*)0, nb);
    bn_fin_kernel<<<1, 64>>>(gamma0, beta0, 0);

    // ---- layer 1 ----
    gemm_kernel<64, 1><<<nb, 256>>>((const float*)0, w1b, (const float*)0, batch, 0, (const int*)0, nb);
    agg_kernel<<<ab, 256>>>(b1b);
    gemm_kernel<64, 3><<<nb, 256>>>((const float*)0, w2b, b2b, batch, 1, (const int*)0, nb);
    bn_fin_kernel<<<1, 64>>>(gamma1, beta1, 1);

    // ---- head ----
    head_kernel<<<GG, 64>>>(wf, bf, wf1, bf1, wf2, bf2, out);
}

// round 14
// speedup vs baseline: 1.5401x; 1.0199x over previous
#include <cuda_runtime.h>
#include <stdint.h>

#define NN 100000
#define EE 1600000
#define FF 128
#define DD 64
#define GG 512
#define TMM 128   // rows per CTA tile
#define AGG_CH 2048

// ---------------- device scratch ----------------
__device__ __align__(16) float g_y[NN * DD];
__device__ __align__(16) float g_z[NN * DD];
__device__ __align__(16) float g_h[NN * DD];
__device__ __align__(16) int g_deg[NN];
__device__ __align__(16) int g_cur[NN + 4];
__device__ __align__(16) int g_rowptr[NN + 4];
__device__ int g_cnt[GG];
__device__ __align__(8) int2 g_epack[EE];
__device__ double g_sq[DD];
__device__ __align__(16) float g_bnp0[2 * DD];
__device__ __align__(16) float g_bnp1[2 * DD];
__device__ __align__(16) float g_pool[2 * GG * DD];

__device__ __forceinline__ void red1(float* p, float x) {
    asm volatile("red.global.add.f32 [%0], %1;" :: "l"(p), "f"(x) : "memory");
}
__device__ __forceinline__ uint32_t smem_u32(const void* p) {
    return (uint32_t)__cvta_generic_to_shared(p);
}
__device__ __forceinline__ void ldm_x4(uint32_t* a, uint32_t addr) {
    asm volatile("ldmatrix.sync.aligned.m8n8.x4.shared.b16 {%0,%1,%2,%3}, [%4];"
                 : "=r"(a[0]), "=r"(a[1]), "=r"(a[2]), "=r"(a[3]) : "r"(addr));
}
__device__ __forceinline__ void ldm_x2t(uint32_t* b, uint32_t addr) {
    asm volatile("ldmatrix.sync.aligned.m8n8.x2.trans.shared.b16 {%0,%1}, [%2];"
                 : "=r"(b[0]), "=r"(b[1]) : "r"(addr));
}
__device__ __forceinline__ void mma16816(float* c, const uint32_t* a, const uint32_t* b) {
    asm volatile("mma.sync.aligned.m16n8k16.row.col.f32.bf16.bf16.f32 "
                 "{%0,%1,%2,%3}, {%4,%5,%6,%7}, {%8,%9}, {%0,%1,%2,%3};"
                 : "+f"(c[0]), "+f"(c[1]), "+f"(c[2]), "+f"(c[3])
                 : "r"(a[0]), "r"(a[1]), "r"(a[2]), "r"(a[3]), "r"(b[0]), "r"(b[1]));
}
__device__ __forceinline__ uint32_t bfpack(float a, float b) {
    return (__float_as_uint(a) >> 16) | (__float_as_uint(b) & 0xFFFF0000u);
}
__device__ __forceinline__ float bfhi(float a) {
    return __uint_as_float(__float_as_uint(a) & 0xFFFF0000u);
}

// ---------------- single-block exclusive scan (int4), zeroes g_deg after use ----------------
__global__ void scan_kernel() {
    __shared__ int part[512];
    const int CH4 = 49;
    int tid = threadIdx.x;
    int b4 = tid * CH4;
    int4* D4 = reinterpret_cast<int4*>(g_deg);
    const int NV4 = NN / 4;
    int s = 0;
    for (int i = 0; i < CH4; i++) {
        int idx = b4 + i;
        if (idx < NV4) {
            int4 d = D4[idx];
            s += d.x + d.y + d.z + d.w;
        }
    }
    part[tid] = s;
    __syncthreads();
    for (int off = 1; off < 512; off <<= 1) {
        int v = (tid >= off) ? part[tid - off] : 0;
        __syncthreads();
        part[tid] += v;
        __syncthreads();
    }
    int run = (tid == 0) ? 0 : part[tid - 1];
    int4* R4 = reinterpret_cast<int4*>(g_rowptr);
    int4* C4 = reinterpret_cast<int4*>(g_cur);
    for (int i = 0; i < CH4; i++) {
        int idx = b4 + i;
        if (idx < NV4) {
            int4 d = D4[idx];
            int4 r;
            r.x = run;
            r.y = r.x + d.x;
            r.z = r.y + d.y;
            r.w = r.z + d.z;
            run = r.w + d.w;
            R4[idx] = r;
            C4[idx] = r;
            D4[idx] = make_int4(0, 0, 0, 0);
        }
    }
    if (tid == 511) g_rowptr[NN] = run;
}

// ---------------- CSR fill: 4 edges/thread for atomic MLP ----------------
__global__ void fill_kernel(const int* __restrict__ ei, const float* __restrict__ ew) {
    int t0 = (blockIdx.x * 256 + threadIdx.x) * 4;
    int src[4], dst[4], pos[4];
    float w[4];
#pragma unroll
    for (int j = 0; j < 4; j++) {
        int e = t0 + j;
        if (e < EE) {
            src[j] = ei[e];
            dst[j] = ei[EE + e];
            w[j] = ew[e];
        }
    }
#pragma unroll
    for (int j = 0; j < 4; j++) {
        int e = t0 + j;
        if (e < EE) pos[j] = atomicAdd(&g_cur[dst[j]], 1);
    }
#pragma unroll
    for (int j = 0; j < 4; j++) {
        int e = t0 + j;
        if (e < EE) g_epack[pos[j]] = make_int2(src[j], __float_as_int(w[j]));
    }
}

// ============ tensor-core GEMM: C[128 x 64] tile of A[N x K] @ W[K x 64] ============
// split-bf16 3-pass: Ah*Bh + Ah*Bl + Al*Bh. Software-pipelined staging.
// MODE 0: A = A_in, write g_y. If hist_ei != null, blocks >= nb_gemm do the histogram.
// MODE 1: A = g_h with BN0 scale/shift on load, write g_y
// MODE 2: A = g_z, epilogue relu+bias, store g_h, stats + pooling via sorted-batch pass
// MODE 3: like 2, no g_h store
template <int K, int MODE>
__global__ __launch_bounds__(256) void gemm_kernel(
    const float* __restrict__ A_in, const float* __restrict__ W,
    const float* __restrict__ bias, const int* __restrict__ batch, int layer,
    const int* __restrict__ hist_ei, int nb_gemm) {
    const int LDA = 20, APL = TMM * LDA;
    const int LDW = 36, WPL = 32 * LDW;
    __shared__ __align__(16) char s_buf[35840];
    __shared__ float s_sq[64];
    __shared__ int s_g[TMM];
    uint32_t* As = reinterpret_cast<uint32_t*>(s_buf);
    uint32_t* Ws = reinterpret_cast<uint32_t*>(s_buf + 2 * TMM * LDA * 4);
    float* Ht = reinterpret_cast<float*>(s_buf);

    if (MODE == 0 && hist_ei != 0 && (int)blockIdx.x >= nb_gemm) {
        int t = (blockIdx.x - nb_gemm) * 256 + threadIdx.x;
        if (t < EE) atomicAdd(&g_deg[hist_ei[EE + t]], 1);
        if (t < NN) atomicAdd(&g_cnt[batch[t]], 1);
        return;
    }

    const float* A = (MODE == 1) ? g_h : ((MODE >= 2) ? g_z : A_in);
    const int KF4 = K / 4;
    int base = blockIdx.x * TMM;
    int tid = threadIdx.x;
    int wid = tid >> 5;
    int lane = tid & 31;
    if (MODE >= 2) {
        if (tid < 64) s_sq[tid] = 0.f;
        for (int i = tid; i < TMM; i += 256) {
            int gn = base + i;
            s_g[i] = batch[gn < NN ? gn : NN - 1];
        }
    }

    float4 ra[4];
    float4 rw[2];
    auto loadA = [&](int kc) {
#pragma unroll
        for (int it = 0; it < 4; it++) {
            int i = tid + it * 256;
            int n = i >> 3, k4 = i & 7;
            int gn = base + n;
            float4 v = make_float4(0.f, 0.f, 0.f, 0.f);
            if (gn < NN) v = reinterpret_cast<const float4*>(A)[(size_t)gn * KF4 + (kc >> 2) + k4];
            if (MODE == 1) {
                int ci = (kc >> 2) + k4;
                float4 sc = reinterpret_cast<const float4*>(g_bnp0)[ci];
                float4 sh = reinterpret_cast<const float4*>(g_bnp0)[16 + ci];
                v.x = v.x * sc.x + sh.x;
                v.y = v.y * sc.y + sh.y;
                v.z = v.z * sc.z + sh.z;
                v.w = v.w * sc.w + sh.w;
            }
            ra[it] = v;
        }
    };
    auto loadW = [&](int kc) {
#pragma unroll
        for (int it = 0; it < 2; it++) {
            int i = tid + it * 256;
            int k = i >> 4, j4 = i & 15;
            rw[it] = reinterpret_cast<const float4*>(W)[(size_t)(kc + k) * 16 + j4];
        }
    };
    auto storeAW = [&]() {
#pragma unroll
        for (int it = 0; it < 4; it++) {
            int i = tid + it * 256;
            int n = i >> 3, k4 = i & 7;
            float4 v = ra[it];
            int off = n * LDA + k4 * 2;
            As[off] = bfpack(v.x, v.y);
            As[off + 1] = bfpack(v.z, v.w);
            As[APL + off] = bfpack(v.x - bfhi(v.x), v.y - bfhi(v.y));
            As[APL + off + 1] = bfpack(v.z - bfhi(v.z), v.w - bfhi(v.w));
        }
#pragma unroll
        for (int it = 0; it < 2; it++) {
            int i = tid + it * 256;
            int k = i >> 4, j4 = i & 15;
            float4 v = rw[it];
            int off = k * LDW + j4 * 2;
            Ws[off] = bfpack(v.x, v.y);
            Ws[off + 1] = bfpack(v.z, v.w);
            Ws[WPL + off] = bfpack(v.x - bfhi(v.x), v.y - bfhi(v.y));
            Ws[WPL + off + 1] = bfpack(v.z - bfhi(v.z), v.w - bfhi(v.w));
        }
    };

    float acc[8][4];
#pragma unroll
    for (int nt = 0; nt < 8; nt++) {
        acc[nt][0] = 0.f; acc[nt][1] = 0.f; acc[nt][2] = 0.f; acc[nt][3] = 0.f;
    }

    loadA(0);
    loadW(0);
    for (int kc = 0; kc < K; kc += 32) {
        storeAW();
        __syncthreads();
        if (kc + 32 < K) {
            loadA(kc + 32);
            loadW(kc + 32);
        }
#pragma unroll
        for (int s = 0; s < 2; s++) {
            uint32_t ah[4], al[4];
            uint32_t aaddr = smem_u32(&As[(wid * 16 + (lane & 15)) * LDA + s * 8 + ((lane >> 4) << 2)]);
            ldm_x4(ah, aaddr);
            ldm_x4(al, aaddr + APL * 4);
#pragma unroll
            for (int nt = 0; nt < 8; nt++) {
                uint32_t bh[2], bl[2];
                uint32_t baddr = smem_u32(&Ws[(s * 16 + (lane & 15)) * LDW + nt * 4]);
                ldm_x2t(bh, baddr);
                ldm_x2t(bl, baddr + WPL * 4);
                mma16816(acc[nt], ah, bh);
                mma16816(acc[nt], ah, bl);
                mma16816(acc[nt], al, bh);
            }
        }
        __syncthreads();
    }

    int rl0 = wid * 16 + (lane >> 2);
    int r0 = base + rl0;
    int cb = (lane & 3) * 2;
    if (MODE <= 1) {
#pragma unroll
        for (int nt = 0; nt < 8; nt++) {
            int col = nt * 8 + cb;
            if (r0 < NN)
                *reinterpret_cast<float2*>(&g_y[r0 * 64 + col]) = make_float2(acc[nt][0], acc[nt][1]);
            if (r0 + 8 < NN)
                *reinterpret_cast<float2*>(&g_y[(r0 + 8) * 64 + col]) = make_float2(acc[nt][2], acc[nt][3]);
        }
    } else {
#pragma unroll
        for (int nt = 0; nt < 8; nt++) {
            int col = nt * 8 + cb;
            float2 bb = *reinterpret_cast<const float2*>(&bias[col]);
#pragma unroll
            for (int h2 = 0; h2 < 2; h2++) {
                int rl = rl0 + h2 * 8;
                int r = base + rl;
                float v0 = 0.f, v1 = 0.f;
                if (r < NN) {
                    v0 = fmaxf(acc[nt][h2 * 2 + 0] + bb.x, 0.f);
                    v1 = fmaxf(acc[nt][h2 * 2 + 1] + bb.y, 0.f);
                    if (MODE == 2)
                        *reinterpret_cast<float2*>(&g_h[r * 64 + col]) = make_float2(v0, v1);
                }
                *reinterpret_cast<float2*>(&Ht[rl * 68 + col]) = make_float2(v0, v1);
            }
        }
        __syncthreads();
        int col = tid & 63;
        int rs = (tid >> 6) * 32;
        float* poolL = &g_pool[layer * GG * DD];
        float ps = 0.f, pq = 0.f;
        int cg = s_g[rs];
#pragma unroll 4
        for (int r = rs; r < rs + 32; r++) {
            float v = Ht[r * 68 + col];
            int gr = s_g[r];
            if (gr != cg) {
                red1(&poolL[cg * 64 + col], ps);
                ps = 0.f;
                cg = gr;
            }
            ps += v;
            pq += v * v;
        }
        red1(&poolL[cg * 64 + col], ps);
        atomicAdd(&s_sq[col], pq);
        __syncthreads();
        if (tid < 64) atomicAdd(&g_sq[tid], (double)s_sq[tid]);
    }
}

// ---------------- CSR aggregation: 32 nodes/block, 8 threads/node, 2 float4/thread ----------------
__global__ __launch_bounds__(256) void agg_kernel(const float* __restrict__ b1) {
    __shared__ int2 s_e[AGG_CH];
    __shared__ int s_ptr[33];
    int nb0 = blockIdx.x * 32;
    int tid = threadIdx.x;
    if (tid <= 32) {
        int n = nb0 + tid;
        s_ptr[tid] = g_rowptr[n > NN ? NN : n];
    }
    __syncthreads();
    int e0 = s_ptr[0];
    int e1 = s_ptr[32];
    int g8 = tid >> 3;            // node index within block (0..31)
    int c = tid & 7;              // float4 column chunk (handles c and c+8)
    int node = nb0 + g8;
    bool valid = node < NN;
    int my_s = valid ? s_ptr[g8] : 0;
    int my_e = valid ? s_ptr[g8 + 1] : 0;
    const float4* Y4 = reinterpret_cast<const float4*>(g_y);
    float4 a0 = make_float4(0.f, 0.f, 0.f, 0.f);
    float4 a1 = a0;
    if (valid) {
        a0 = Y4[node * 16 + c];
        a1 = Y4[node * 16 + c + 8];
    }
    for (int cs = e0; cs < e1; cs += AGG_CH) {
        int ce = min(cs + AGG_CH, e1);
        __syncthreads();
        for (int i = tid; i < ce - cs; i += 256) s_e[i] = g_epack[cs + i];
        __syncthreads();
        int lo = max(my_s, cs);
        int hi = min(my_e, ce);
        int i = lo;
        for (; i + 2 <= hi; i += 2) {
            int2 ea = s_e[i - cs];
            int2 eb = s_e[i + 1 - cs];
            int ba = ea.x * 16 + c;
            int bb = eb.x * 16 + c;
            float4 va0 = Y4[ba];
            float4 va1 = Y4[ba + 8];
            float4 vb0 = Y4[bb];
            float4 vb1 = Y4[bb + 8];
            float wa = __int_as_float(ea.y);
            float wb = __int_as_float(eb.y);
            a0.x += wa * va0.x + wb * vb0.x;
            a0.y += wa * va0.y + wb * vb0.y;
            a0.z += wa * va0.z + wb * vb0.z;
            a0.w += wa * va0.w + wb * vb0.w;
            a1.x += wa * va1.x + wb * vb1.x;
            a1.y += wa * va1.y + wb * vb1.y;
            a1.z += wa * va1.z + wb * vb1.z;
            a1.w += wa * va1.w + wb * vb1.w;
        }
        if (i < hi) {
            int2 ea = s_e[i - cs];
            int ba = ea.x * 16 + c;
            float4 va0 = Y4[ba];
            float4 va1 = Y4[ba + 8];
            float wa = __int_as_float(ea.y);
            a0.x += wa * va0.x;
            a0.y += wa * va0.y;
            a0.z += wa * va0.z;
            a0.w += wa * va0.w;
            a1.x += wa * va1.x;
            a1.y += wa * va1.y;
            a1.z += wa * va1.z;
            a1.w += wa * va1.w;
        }
    }
    if (valid) {
        float4 b0 = reinterpret_cast<const float4*>(b1)[c];
        float4 b14 = reinterpret_cast<const float4*>(b1)[c + 8];
        reinterpret_cast<float4*>(g_z)[node * 16 + c] =
            make_float4(fmaxf(a0.x + b0.x, 0.f), fmaxf(a0.y + b0.y, 0.f),
                        fmaxf(a0.z + b0.z, 0.f), fmaxf(a0.w + b0.w, 0.f));
        reinterpret_cast<float4*>(g_z)[node * 16 + c + 8] =
            make_float4(fmaxf(a1.x + b14.x, 0.f), fmaxf(a1.y + b14.y, 0.f),
                        fmaxf(a1.z + b14.z, 0.f), fmaxf(a1.w + b14.w, 0.f));
    }
}

// ---------------- BN finalize: mean from pool, var from g_sq; resets g_sq ----------------
__global__ void bn_fin_kernel(const float* __restrict__ gamma, const float* __restrict__ beta,
                              int layer) {
    int f = threadIdx.x;
    if (f >= DD) return;
    const float* pp = &g_pool[layer * GG * DD];
    float s0 = 0.f, s1 = 0.f, s2 = 0.f, s3 = 0.f;
    for (int g = 0; g < GG; g += 4) {
        s0 += pp[(g + 0) * DD + f];
        s1 += pp[(g + 1) * DD + f];
        s2 += pp[(g + 2) * DD + f];
        s3 += pp[(g + 3) * DD + f];
    }
    float s = (s0 + s1) + (s2 + s3);
    double q = g_sq[f];
    g_sq[f] = 0.0;
    float mu = s / (float)NN;
    float var = (float)(q / (double)NN) - mu * mu;
    float rstd = rsqrtf(var + 1e-5f);
    float sc = gamma[f] * rstd;
    float* bp = layer ? g_bnp1 : g_bnp0;
    bp[f] = sc;
    bp[DD + f] = beta[f] - mu * sc;
}

// ---------------- classifier head; self-cleans g_pool and g_cnt ----------------
__global__ void head_kernel(const float* __restrict__ wf, const float* __restrict__ bf,
                            const float* __restrict__ wf1, const float* __restrict__ bf1,
                            const float* __restrict__ wf2, const float* __restrict__ bf2,
                            float* __restrict__ out) {
    __shared__ float gs[128];
    __shared__ float as_[64];
    __shared__ float bs[64];
    int g = blockIdx.x;
    int j = threadIdx.x;
    float cnt = (float)g_cnt[g];
    gs[j]      = g_pool[g * 64 + j] * g_bnp0[j] + cnt * g_bnp0[64 + j];
    gs[64 + j] = g_pool[(GG + g) * 64 + j] * g_bnp1[j] + cnt * g_bnp1[64 + j];
    g_pool[g * 64 + j] = 0.f;
    g_pool[(GG + g) * 64 + j] = 0.f;
    if (j == 0) g_cnt[g] = 0;
    __syncthreads();
    float acc = bf[j];
#pragma unroll 8
    for (int k = 0; k < 128; k++) acc += gs[k] * wf[k * 64 + j];
    as_[j] = fmaxf(acc, 0.f);
    __syncthreads();
    acc = bf1[j];
#pragma unroll 8
    for (int k = 0; k < 64; k++) acc += as_[k] * wf1[k * 64 + j];
    bs[j] = fmaxf(acc, 0.f);
    __syncthreads();
    if (j == 0) {
        float l0 = bf2[0], l1 = bf2[1];
        for (int k = 0; k < 64; k++) {
            l0 += bs[k] * wf2[k * 2 + 0];
            l1 += bs[k] * wf2[k * 2 + 1];
        }
        float m = fmaxf(l0, l1);
        float lse = m + logf(expf(l0 - m) + expf(l1 - m));
        out[g * 2 + 0] = l0 - lse;
        out[g * 2 + 1] = l1 - lse;
    }
}

extern "C" void kernel_launch(void* const* d_in, const int* in_sizes, int n_in,
                              void* d_out, int out_size) {
    (void)in_sizes; (void)n_in; (void)out_size;
    const float* x     = (const float*)d_in[0];
    const int*   ei    = (const int*)d_in[1];
    const float* ew    = (const float*)d_in[2];
    const int*   batch = (const int*)d_in[3];
    const float* w1a = (const float*)d_in[4];
    const float* b1a = (const float*)d_in[5];
    const float* w2a = (const float*)d_in[6];
    const float* b2a = (const float*)d_in[7];
    const float* gamma0 = (const float*)d_in[8];
    const float* beta0  = (const float*)d_in[9];
    const float* w1b = (const float*)d_in[10];
    const float* b1b = (const float*)d_in[11];
    const float* w2b = (const float*)d_in[12];
    const float* b2b = (const float*)d_in[13];
    const float* gamma1 = (const float*)d_in[14];
    const float* beta1  = (const float*)d_in[15];
    const float* wf  = (const float*)d_in[16];
    const float* bf  = (const float*)d_in[17];
    const float* wf1 = (const float*)d_in[18];
    const float* bf1 = (const float*)d_in[19];
    const float* wf2 = (const float*)d_in[20];
    const float* bf2 = (const float*)d_in[21];
    float* out = (float*)d_out;

    int nb = (NN + TMM - 1) / TMM;         // 782
    int eb = (EE + 255) / 256;             // 6250
    int eb4 = (EE + 1023) / 1024;          // 1563
    int ab = (NN + 31) / 32;               // 3125

    // ---- layer 0 projection + fused degree/count histogram ----
    gemm_kernel<128, 0><<<nb + eb, 256>>>(x, w1a, (const float*)0, batch, 0, ei, nb);
    scan_kernel<<<1, 512>>>();
    fill_kernel<<<eb4, 256>>>(ei, ew);
    agg_kernel<<<ab, 256>>>(b1a);
    gemm_kernel<64, 2><<<nb, 256>>>((const float*)0, w2a, b2a, batch, 0, (const int*)0, nb);
    bn_fin_kernel<<<1, 64>>>(gamma0, beta0, 0);

    // ---- layer 1 ----
    gemm_kernel<64, 1><<<nb, 256>>>((const float*)0, w1b, (const float*)0, batch, 0, (const int*)0, nb);
    agg_kernel<<<ab, 256>>>(b1b);
    gemm_kernel<64, 3><<<nb, 256>>>((const float*)0, w2b, b2b, batch, 1, (const int*)0, nb);
    bn_fin_kernel<<<1, 64>>>(gamma1, beta1, 1);

    // ---- head ----
    head_kernel<<<GG, 64>>>(wf, bf, wf1, bf1, wf2, bf2, out);
}